// round 5
// baseline (speedup 1.0000x reference)
#include <cuda_runtime.h>
#include <cstdint>

#define B_ 4096
#define T_ 120
#define I_ 64
#define H_ 128
#define G_ 384   // 3*H

// Scratch for input-side gate pre-activations, layout [t][B][G],
// gate-interleaved columns: col' = j*3 + gate, gate in {r=0,z=1,n=2}
__device__ float g_xg[(size_t)B_ * T_ * G_];

// ---- packed f32x2 helpers ----
#define FMA2(d, a, b) \
    asm("fma.rn.f32x2 %0, %1, %2, %0;" : "+l"(d) : "l"(a), "l"(b))

#define PACK2(p, f) do {                                            \
    unsigned int _u = __float_as_uint(f);                           \
    asm("mov.b64 %0, {%1, %2};" : "=l"(p) : "r"(_u), "r"(_u));      \
} while (0)

#define UNPACK2(lo, hi, p) do {                                     \
    unsigned int _l, _h;                                            \
    asm("mov.b64 {%0, %1}, %2;" : "=r"(_l), "=r"(_h) : "l"(p));     \
    (lo) = __uint_as_float(_l); (hi) = __uint_as_float(_h);         \
} while (0)

#define TANHA(y, x) asm("tanh.approx.f32 %0, %1;" : "=f"(y) : "f"(x))

__device__ __forceinline__ float sigmoid_mufu(float x) {
    float th; TANHA(th, 0.5f * x);
    return fmaf(0.5f, th, 0.5f);
}
__device__ __forceinline__ float tanh_mufu(float x) {
    float th; TANHA(th, x);
    return th;
}

// =====================================================================
// Kernel 1: x_gates = x @ W_ih^T + b_ih  -> g_xg[t][B][G]
// 256 threads, 64 rows x 384 cols, tile 8 rows x 12 cols, single pass.
// x duplicated in smem -> zero packing in inner loop.
// =====================================================================
#define K1_SMEM ((64 * G_ + 64 * 128 + G_) * 4)   // 132608 B

__global__ __launch_bounds__(256, 1) void k1_xgates(
    const float* __restrict__ x,
    const float* __restrict__ Wih,
    const float* __restrict__ bih)
{
    extern __shared__ float sm[];
    float* Wt = sm;               // [64][384]  WihT[i][col']
    float* xd = Wt + 64 * G_;     // [64][128]  x dup: [i][2r],[i][2r+1]
    float* bI = xd + 64 * 128;    // [384] reordered bias

    const int tid = threadIdx.x;
    const size_t r0 = (size_t)blockIdx.x * 64;

    for (int idx = tid; idx < G_ * I_; idx += 256) {
        int g = idx >> 6, i = idx & 63;
        Wt[i * G_ + ((g & 127) * 3 + (g >> 7))] = Wih[idx];
    }
    for (int g = tid; g < G_; g += 256)
        bI[(g & 127) * 3 + (g >> 7)] = bih[g];
    for (int idx = tid; idx < 64 * I_; idx += 256) {
        int r = idx >> 6, i = idx & 63;
        float v = x[(r0 + r) * I_ + i];
        *(float2*)(xd + i * 128 + 2 * r) = make_float2(v, v);
    }
    __syncthreads();

    const int mblk = tid & 7;     // 8 blocks of 8 rows
    const int jblk = tid >> 3;    // 32 blocks of 12 cols
    const int m0 = mblk * 8;
    const int c0 = jblk * 12;

    unsigned long long acc[8][6];
    #pragma unroll
    for (int c = 0; c < 6; c++) {
        unsigned long long bp = *(const unsigned long long*)(bI + c0 + 2 * c);
        #pragma unroll
        for (int p = 0; p < 8; p++) acc[p][c] = bp;
    }

    #pragma unroll 4
    for (int k = 0; k < 64; k++) {
        const float* xrow = xd + k * 128 + 16 * mblk;   // 8 dup pairs = 64B
        ulonglong2 xa = *(const ulonglong2*)(xrow);
        ulonglong2 xb = *(const ulonglong2*)(xrow + 4);
        ulonglong2 xc = *(const ulonglong2*)(xrow + 8);
        ulonglong2 xe = *(const ulonglong2*)(xrow + 12);
        unsigned long long hp[8] = {xa.x, xa.y, xb.x, xb.y,
                                    xc.x, xc.y, xe.x, xe.y};
        const float* wrow = Wt + k * G_ + c0;
        ulonglong2 wa = *(const ulonglong2*)(wrow);
        ulonglong2 wb = *(const ulonglong2*)(wrow + 4);
        ulonglong2 wc = *(const ulonglong2*)(wrow + 8);
        unsigned long long wp[6] = {wa.x, wa.y, wb.x, wb.y, wc.x, wc.y};
        #pragma unroll
        for (int p = 0; p < 8; p++) {
            #pragma unroll
            for (int c = 0; c < 6; c++) FMA2(acc[p][c], hp[p], wp[c]);
        }
    }

    #pragma unroll
    for (int p = 0; p < 8; p++) {
        float v[12];
        #pragma unroll
        for (int c = 0; c < 6; c++) UNPACK2(v[2 * c], v[2 * c + 1], acc[p][c]);
        unsigned int r = (unsigned int)(r0 + m0 + p);
        unsigned int b = r / T_, t = r % T_;
        float* dst = g_xg + ((size_t)t * B_ + b) * G_ + c0;
        *(float4*)(dst)     = make_float4(v[0], v[1], v[2],  v[3]);
        *(float4*)(dst + 4) = make_float4(v[4], v[5], v[6],  v[7]);
        *(float4*)(dst + 8) = make_float4(v[8], v[9], v[10], v[11]);
    }
}

// =====================================================================
// Kernel 2: recurrence. 128 CTAs x 32 batch rows, 256 threads.
// Tile: 4 rows x 12 cols. Double-buffered h -> ONE sync per step.
// =====================================================================
#define K2_SMEM ((128 * G_ + 2 * 128 * 32 + G_) * 4)   // 230912 B

__global__ __launch_bounds__(256, 1) void k2_recur(
    const float* __restrict__ Whh,
    const float* __restrict__ bhh,
    float* __restrict__ out,      // [B, T, H]
    float* __restrict__ hT_out)   // [B, H]
{
    extern __shared__ float sm[];
    float* Wt    = sm;                    // [128][384]  WhhT[k][col']
    float* hbuf0 = Wt + 128 * G_;         // [128][32]   h, buffer 0
    float* hbuf1 = hbuf0 + 128 * 32;      // [128][32]   h, buffer 1
    float* bI    = hbuf1 + 128 * 32;      // [384] reordered bias

    const int tid = threadIdx.x;
    const size_t b0 = (size_t)blockIdx.x * 32;

    for (int idx = tid; idx < G_ * H_; idx += 256) {
        int g = idx >> 7, k = idx & 127;
        Wt[k * G_ + ((g & 127) * 3 + (g >> 7))] = Whh[idx];
    }
    for (int g = tid; g < G_; g += 256)
        bI[(g & 127) * 3 + (g >> 7)] = bhh[g];
    for (int idx = tid; idx < 128 * 32; idx += 256) hbuf0[idx] = 0.0f;
    __syncthreads();

    const int mblk = tid & 7;     // 8 blocks of 4 rows
    const int jblk = tid >> 3;    // 32 blocks of 12 cols
    const int m0 = mblk * 4;
    const int c0 = jblk * 12;
    const int j0 = jblk * 4;
    const size_t row0 = b0 + m0;

    unsigned long long bias[6];
    #pragma unroll
    for (int c = 0; c < 6; c++)
        bias[c] = *(const unsigned long long*)(bI + c0 + 2 * c);

    float hprev[4][4];
    #pragma unroll
    for (int mi = 0; mi < 4; mi++)
        #pragma unroll
        for (int ji = 0; ji < 4; ji++) hprev[mi][ji] = 0.0f;

    for (int t = 0; t < T_; t++) {
        float* cur = (t & 1) ? hbuf1 : hbuf0;
        float* nxt = (t & 1) ? hbuf0 : hbuf1;

        // Prefetch input-side gate values (LDG hidden behind GEMM)
        float xf[4][12];
        #pragma unroll
        for (int mi = 0; mi < 4; mi++) {
            const float* p = g_xg + ((size_t)t * B_ + row0 + mi) * G_ + c0;
            float4 a = *(const float4*)(p);
            float4 b = *(const float4*)(p + 4);
            float4 c = *(const float4*)(p + 8);
            xf[mi][0] = a.x; xf[mi][1]  = a.y; xf[mi][2]  = a.z; xf[mi][3]  = a.w;
            xf[mi][4] = b.x; xf[mi][5]  = b.y; xf[mi][6]  = b.z; xf[mi][7]  = b.w;
            xf[mi][8] = c.x; xf[mi][9]  = c.y; xf[mi][10] = c.z; xf[mi][11] = c.w;
        }

        // hg = h @ W_hh^T + b_hh; acc[row][colpair]
        unsigned long long acc[4][6];
        #pragma unroll
        for (int r = 0; r < 4; r++)
            #pragma unroll
            for (int c = 0; c < 6; c++) acc[r][c] = bias[c];

        #pragma unroll 4
        for (int k = 0; k < 128; k++) {
            float4 hv = *(const float4*)(cur + k * 32 + m0);  // 1 wavefront
            unsigned long long hp[4];
            PACK2(hp[0], hv.x); PACK2(hp[1], hv.y);
            PACK2(hp[2], hv.z); PACK2(hp[3], hv.w);
            const float* wrow = Wt + k * G_ + c0;
            ulonglong2 wa = *(const ulonglong2*)(wrow);
            ulonglong2 wb = *(const ulonglong2*)(wrow + 4);
            ulonglong2 wc = *(const ulonglong2*)(wrow + 8);
            unsigned long long wp[6] = {wa.x, wa.y, wb.x, wb.y, wc.x, wc.y};
            #pragma unroll
            for (int r = 0; r < 4; r++) {
                #pragma unroll
                for (int c = 0; c < 6; c++) FMA2(acc[r][c], hp[r], wp[c]);
            }
        }

        float hg[4][12];
        #pragma unroll
        for (int r = 0; r < 4; r++)
            #pragma unroll
            for (int c = 0; c < 6; c++)
                UNPACK2(hg[r][2 * c], hg[r][2 * c + 1], acc[r][c]);

        #pragma unroll
        for (int mi = 0; mi < 4; mi++) {
            float o[4];
            #pragma unroll
            for (int ji = 0; ji < 4; ji++) {
                float r = sigmoid_mufu(xf[mi][ji * 3 + 0] + hg[mi][ji * 3 + 0]);
                float z = sigmoid_mufu(xf[mi][ji * 3 + 1] + hg[mi][ji * 3 + 1]);
                float n = tanh_mufu(xf[mi][ji * 3 + 2] + r * hg[mi][ji * 3 + 2]);
                float h = n + z * (hprev[mi][ji] - n);
                hprev[mi][ji] = h;
                o[ji] = h;
            }
            *(float4*)(out + ((row0 + mi) * (size_t)T_ + t) * H_ + j0) =
                make_float4(o[0], o[1], o[2], o[3]);
        }

        // Publish h for next step into the OTHER buffer
        #pragma unroll
        for (int ji = 0; ji < 4; ji++)
            *(float4*)(nxt + (j0 + ji) * 32 + m0) =
                make_float4(hprev[0][ji], hprev[1][ji], hprev[2][ji], hprev[3][ji]);
        __syncthreads();   // single barrier: covers RAW (nxt) and WAR (cur)
    }

    #pragma unroll
    for (int mi = 0; mi < 4; mi++)
        *(float4*)(hT_out + (row0 + mi) * H_ + j0) =
            make_float4(hprev[mi][0], hprev[mi][1], hprev[mi][2], hprev[mi][3]);
}

extern "C" void kernel_launch(void* const* d_in, const int* in_sizes, int n_in,
                              void* d_out, int out_size)
{
    const float* x   = (const float*)d_in[0];
    const float* Wih = (const float*)d_in[1];
    const float* Whh = (const float*)d_in[2];
    const float* bih = (const float*)d_in[3];
    const float* bhh = (const float*)d_in[4];

    float* out = (float*)d_out;                       // [B, T, H]
    float* hT  = out + (size_t)B_ * T_ * H_;          // [B, H]

    cudaFuncSetAttribute(k1_xgates, cudaFuncAttributeMaxDynamicSharedMemorySize, K1_SMEM);
    cudaFuncSetAttribute(k2_recur,  cudaFuncAttributeMaxDynamicSharedMemorySize, K2_SMEM);

    k1_xgates<<<(B_ * T_) / 64, 256, K1_SMEM>>>(x, Wih, bih);
    k2_recur<<<B_ / 32, 256, K2_SMEM>>>(Whh, bhh, out, hT);
}

// round 6
// speedup vs baseline: 1.3650x; 1.3650x over previous
#include <cuda_runtime.h>
#include <cstdint>

#define B_ 4096
#define T_ 120
#define I_ 64
#define H_ 128
#define G_ 384   // 3*H

#define NTILE ((B_ * T_) / 128)          // 3840 row-tiles for K1
#define K1_GRID 148
#define K1_ITER ((NTILE + K1_GRID - 1) / K1_GRID)   // 26

// Scratch for input-side gate pre-activations, layout [t][B][G],
// gate-interleaved columns: col' = j*3 + gate, gate in {r=0,z=1,n=2}
__device__ float g_xg[(size_t)B_ * T_ * G_];

// ---- packed f32x2 helpers ----
#define FMA2(d, a, b) \
    asm("fma.rn.f32x2 %0, %1, %2, %0;" : "+l"(d) : "l"(a), "l"(b))

#define PACK2(p, f) do {                                            \
    unsigned int _u = __float_as_uint(f);                           \
    asm("mov.b64 %0, {%1, %2};" : "=l"(p) : "r"(_u), "r"(_u));      \
} while (0)

#define UNPACK2(lo, hi, p) do {                                     \
    unsigned int _l, _h;                                            \
    asm("mov.b64 {%0, %1}, %2;" : "=r"(_l), "=r"(_h) : "l"(p));     \
    (lo) = __uint_as_float(_l); (hi) = __uint_as_float(_h);         \
} while (0)

#define TANHA(y, x) asm("tanh.approx.f32 %0, %1;" : "=f"(y) : "f"(x))

__device__ __forceinline__ float sigmoid_mufu(float x) {
    float th; TANHA(th, 0.5f * x);
    return fmaf(0.5f, th, 0.5f);
}
__device__ __forceinline__ float tanh_mufu(float x) {
    float th; TANHA(th, x);
    return th;
}

// =====================================================================
// Kernel 1 (persistent): x_gates = x @ W_ih^T + b_ih -> g_xg[t][B][G]
// 148 CTAs x 256 threads. W_ih^T resident in smem for all tiles.
// Per tile: 128 rows x 384 cols, thread tile 8 rows x 12 cols, 2 halves.
// x stored duplicated -> zero packing in inner loop.
// =====================================================================
#define K1_SMEM ((64 * G_ + 64 * 256 + G_) * 4)   // 165376 B

__global__ __launch_bounds__(256, 1) void k1_xgates(
    const float* __restrict__ x,
    const float* __restrict__ Wih,
    const float* __restrict__ bih)
{
    extern __shared__ float sm[];
    float* Wt = sm;               // [64][384]  WihT[i][col']
    float* xd = Wt + 64 * G_;     // [64][256]  x dup: [i][2r],[i][2r+1]
    float* bI = xd + 64 * 256;    // [384] reordered bias

    const int tid = threadIdx.x;

    // One-time: W_ih reordered+transposed, bias reordered
    for (int idx = tid; idx < G_ * I_; idx += 256) {
        int g = idx >> 6, i = idx & 63;
        Wt[i * G_ + ((g & 127) * 3 + (g >> 7))] = Wih[idx];
    }
    for (int g = tid; g < G_; g += 256)
        bI[(g & 127) * 3 + (g >> 7)] = bih[g];

    const int mblk = tid & 15;       // 16 row blocks of 8
    const int jblk = tid >> 4;       // 16 col blocks of 12 (per half)
    const int m0 = mblk * 8;

    for (int it = 0; it < K1_ITER; it++) {
        const int tt = blockIdx.x + it * K1_GRID;
        if (tt >= NTILE) break;
        const size_t r0 = (size_t)tt * 128;

        // Load x tile [128][64] -> duplicated transposed smem
        __syncthreads();   // prior tile's reads of xd complete
        for (int idx = tid; idx < 128 * 16; idx += 256) {
            int r = idx >> 4, i4 = idx & 15;
            float4 v = *(const float4*)(x + (r0 + r) * I_ + 4 * i4);
            *(float2*)(xd + (4 * i4 + 0) * 256 + 2 * r) = make_float2(v.x, v.x);
            *(float2*)(xd + (4 * i4 + 1) * 256 + 2 * r) = make_float2(v.y, v.y);
            *(float2*)(xd + (4 * i4 + 2) * 256 + 2 * r) = make_float2(v.z, v.z);
            *(float2*)(xd + (4 * i4 + 3) * 256 + 2 * r) = make_float2(v.w, v.w);
        }
        __syncthreads();

        for (int half = 0; half < 2; half++) {
            const int c0 = half * 192 + jblk * 12;

            unsigned long long acc[8][6];
            #pragma unroll
            for (int c = 0; c < 6; c++) {
                unsigned long long bp =
                    *(const unsigned long long*)(bI + c0 + 2 * c);
                #pragma unroll
                for (int p = 0; p < 8; p++) acc[p][c] = bp;
            }

            #pragma unroll 4
            for (int k = 0; k < 64; k++) {
                const float* xrow = xd + k * 256 + 16 * mblk;  // 8 dup pairs
                ulonglong2 xa = *(const ulonglong2*)(xrow);
                ulonglong2 xb = *(const ulonglong2*)(xrow + 4);
                ulonglong2 xc = *(const ulonglong2*)(xrow + 8);
                ulonglong2 xe = *(const ulonglong2*)(xrow + 12);
                unsigned long long hp[8] = {xa.x, xa.y, xb.x, xb.y,
                                            xc.x, xc.y, xe.x, xe.y};
                const float* wrow = Wt + k * G_ + c0;
                ulonglong2 wa = *(const ulonglong2*)(wrow);
                ulonglong2 wb = *(const ulonglong2*)(wrow + 4);
                ulonglong2 wc = *(const ulonglong2*)(wrow + 8);
                unsigned long long wp[6] = {wa.x, wa.y, wb.x, wb.y, wc.x, wc.y};
                #pragma unroll
                for (int p = 0; p < 8; p++) {
                    #pragma unroll
                    for (int c = 0; c < 6; c++) FMA2(acc[p][c], hp[p], wp[c]);
                }
            }

            #pragma unroll
            for (int p = 0; p < 8; p++) {
                float v[12];
                #pragma unroll
                for (int c = 0; c < 6; c++)
                    UNPACK2(v[2 * c], v[2 * c + 1], acc[p][c]);
                unsigned int r = (unsigned int)(r0 + m0 + p);
                unsigned int b = r / T_, t = r % T_;
                float* dst = g_xg + ((size_t)t * B_ + b) * G_ + c0;
                *(float4*)(dst)     = make_float4(v[0], v[1], v[2],  v[3]);
                *(float4*)(dst + 4) = make_float4(v[4], v[5], v[6],  v[7]);
                *(float4*)(dst + 8) = make_float4(v[8], v[9], v[10], v[11]);
            }
        }
    }
}

// =====================================================================
// Kernel 2: recurrence. 128 CTAs x 32 batch rows, 256 threads.
// Tile 4 rows x 12 cols. Double-buffered h, ONE sync per step.
// Register double-buffered operand loads (k+1 prefetch).
// =====================================================================
#define K2_SMEM ((128 * G_ + 2 * 128 * 32 + G_) * 4)   // 230912 B

__global__ __launch_bounds__(256, 1) void k2_recur(
    const float* __restrict__ Whh,
    const float* __restrict__ bhh,
    float* __restrict__ out,      // [B, T, H]
    float* __restrict__ hT_out)   // [B, H]
{
    extern __shared__ float sm[];
    float* Wt    = sm;                    // [128][384]  WhhT[k][col']
    float* hbuf0 = Wt + 128 * G_;         // [128][32]   h, buffer 0
    float* hbuf1 = hbuf0 + 128 * 32;      // [128][32]   h, buffer 1
    float* bI    = hbuf1 + 128 * 32;      // [384] reordered bias

    const int tid = threadIdx.x;
    const size_t b0 = (size_t)blockIdx.x * 32;

    for (int idx = tid; idx < G_ * H_; idx += 256) {
        int g = idx >> 7, k = idx & 127;
        Wt[k * G_ + ((g & 127) * 3 + (g >> 7))] = Whh[idx];
    }
    for (int g = tid; g < G_; g += 256)
        bI[(g & 127) * 3 + (g >> 7)] = bhh[g];
    for (int idx = tid; idx < 128 * 32; idx += 256) hbuf0[idx] = 0.0f;
    __syncthreads();

    const int mblk = tid & 7;     // 8 blocks of 4 rows
    const int jblk = tid >> 3;    // 32 blocks of 12 cols
    const int m0 = mblk * 4;
    const int c0 = jblk * 12;
    const int j0 = jblk * 4;
    const size_t row0 = b0 + m0;

    unsigned long long bias[6];
    #pragma unroll
    for (int c = 0; c < 6; c++)
        bias[c] = *(const unsigned long long*)(bI + c0 + 2 * c);

    float hprev[4][4];
    #pragma unroll
    for (int mi = 0; mi < 4; mi++)
        #pragma unroll
        for (int ji = 0; ji < 4; ji++) hprev[mi][ji] = 0.0f;

    const float* wbase = Wt + c0;

    for (int t = 0; t < T_; t++) {
        float* cur = (t & 1) ? hbuf1 : hbuf0;
        float* nxt = (t & 1) ? hbuf0 : hbuf1;

        // Prefetch input-side gate values (consumed after k-loop)
        float xf[4][12];
        #pragma unroll
        for (int mi = 0; mi < 4; mi++) {
            const float* p = g_xg + ((size_t)t * B_ + row0 + mi) * G_ + c0;
            float4 a = *(const float4*)(p);
            float4 b = *(const float4*)(p + 4);
            float4 c = *(const float4*)(p + 8);
            xf[mi][0] = a.x; xf[mi][1]  = a.y; xf[mi][2]  = a.z; xf[mi][3]  = a.w;
            xf[mi][4] = b.x; xf[mi][5]  = b.y; xf[mi][6]  = b.z; xf[mi][7]  = b.w;
            xf[mi][8] = c.x; xf[mi][9]  = c.y; xf[mi][10] = c.z; xf[mi][11] = c.w;
        }

        unsigned long long acc[4][6];
        #pragma unroll
        for (int r = 0; r < 4; r++)
            #pragma unroll
            for (int c = 0; c < 6; c++) acc[r][c] = bias[c];

        // k-loop with register double-buffered operands
        float4 hv = *(const float4*)(cur + m0);
        ulonglong2 wa = *(const ulonglong2*)(wbase);
        ulonglong2 wb = *(const ulonglong2*)(wbase + 4);
        ulonglong2 wc = *(const ulonglong2*)(wbase + 8);

        #pragma unroll 8
        for (int k = 0; k < 128; k++) {
            const int kn = (k + 1) & 127;
            float4 hv_n = *(const float4*)(cur + kn * 32 + m0);
            const float* wn = wbase + kn * G_;
            ulonglong2 wa_n = *(const ulonglong2*)(wn);
            ulonglong2 wb_n = *(const ulonglong2*)(wn + 4);
            ulonglong2 wc_n = *(const ulonglong2*)(wn + 8);

            unsigned long long hp[4];
            PACK2(hp[0], hv.x); PACK2(hp[1], hv.y);
            PACK2(hp[2], hv.z); PACK2(hp[3], hv.w);
            unsigned long long wp[6] = {wa.x, wa.y, wb.x, wb.y, wc.x, wc.y};
            #pragma unroll
            for (int r = 0; r < 4; r++) {
                #pragma unroll
                for (int c = 0; c < 6; c++) FMA2(acc[r][c], hp[r], wp[c]);
            }
            hv = hv_n; wa = wa_n; wb = wb_n; wc = wc_n;
        }

        float hg[4][12];
        #pragma unroll
        for (int r = 0; r < 4; r++)
            #pragma unroll
            for (int c = 0; c < 6; c++)
                UNPACK2(hg[r][2 * c], hg[r][2 * c + 1], acc[r][c]);

        #pragma unroll
        for (int mi = 0; mi < 4; mi++) {
            float o[4];
            #pragma unroll
            for (int ji = 0; ji < 4; ji++) {
                float r = sigmoid_mufu(xf[mi][ji * 3 + 0] + hg[mi][ji * 3 + 0]);
                float z = sigmoid_mufu(xf[mi][ji * 3 + 1] + hg[mi][ji * 3 + 1]);
                float n = tanh_mufu(xf[mi][ji * 3 + 2] + r * hg[mi][ji * 3 + 2]);
                float h = n + z * (hprev[mi][ji] - n);
                hprev[mi][ji] = h;
                o[ji] = h;
            }
            *(float4*)(out + ((row0 + mi) * (size_t)T_ + t) * H_ + j0) =
                make_float4(o[0], o[1], o[2], o[3]);
        }

        // Publish h for next step into the OTHER buffer
        #pragma unroll
        for (int ji = 0; ji < 4; ji++)
            *(float4*)(nxt + (j0 + ji) * 32 + m0) =
                make_float4(hprev[0][ji], hprev[1][ji], hprev[2][ji], hprev[3][ji]);
        __syncthreads();   // covers RAW (nxt) and WAR (cur)
    }

    #pragma unroll
    for (int mi = 0; mi < 4; mi++)
        *(float4*)(hT_out + (row0 + mi) * H_ + j0) =
            make_float4(hprev[mi][0], hprev[mi][1], hprev[mi][2], hprev[mi][3]);
}

extern "C" void kernel_launch(void* const* d_in, const int* in_sizes, int n_in,
                              void* d_out, int out_size)
{
    const float* x   = (const float*)d_in[0];
    const float* Wih = (const float*)d_in[1];
    const float* Whh = (const float*)d_in[2];
    const float* bih = (const float*)d_in[3];
    const float* bhh = (const float*)d_in[4];

    float* out = (float*)d_out;                       // [B, T, H]
    float* hT  = out + (size_t)B_ * T_ * H_;          // [B, H]

    cudaFuncSetAttribute(k1_xgates, cudaFuncAttributeMaxDynamicSharedMemorySize, K1_SMEM);
    cudaFuncSetAttribute(k2_recur,  cudaFuncAttributeMaxDynamicSharedMemorySize, K2_SMEM);

    k1_xgates<<<K1_GRID, 256, K1_SMEM>>>(x, Wih, bih);
    k2_recur<<<B_ / 32, 256, K2_SMEM>>>(Whh, bhh, out, hT);
}

// round 7
// speedup vs baseline: 1.5441x; 1.1312x over previous
#include <cuda_runtime.h>
#include <cstdint>

#define B_ 4096
#define T_ 120
#define I_ 64
#define H_ 128
#define G_ 384   // 3*H

// Scratch for input-side gate pre-activations, layout [t][B][G],
// gate-interleaved columns: col' = j*3 + gate, gate in {r=0,z=1,n=2}
__device__ float g_xg[(size_t)B_ * T_ * G_];

// ---- packed f32x2 helpers ----
#define FMA2(d, a, b) \
    asm("fma.rn.f32x2 %0, %1, %2, %0;" : "+l"(d) : "l"(a), "l"(b))

#define ADD2(d, a) \
    asm("add.rn.f32x2 %0, %0, %1;" : "+l"(d) : "l"(a))

#define PACK2(p, f) do {                                            \
    unsigned int _u = __float_as_uint(f);                           \
    asm("mov.b64 %0, {%1, %2};" : "=l"(p) : "r"(_u), "r"(_u));      \
} while (0)

#define PACKAB(p, flo, fhi) do {                                    \
    unsigned int _lo = __float_as_uint(flo), _hi = __float_as_uint(fhi); \
    asm("mov.b64 %0, {%1, %2};" : "=l"(p) : "r"(_lo), "r"(_hi));    \
} while (0)

#define UNPACK2(lo, hi, p) do {                                     \
    unsigned int _l, _h;                                            \
    asm("mov.b64 {%0, %1}, %2;" : "=r"(_l), "=r"(_h) : "l"(p));     \
    (lo) = __uint_as_float(_l); (hi) = __uint_as_float(_h);         \
} while (0)

#define TANHA(y, x) asm("tanh.approx.f32 %0, %1;" : "=f"(y) : "f"(x))

__device__ __forceinline__ float sigmoid_mufu(float x) {
    float th; TANHA(th, 0.5f * x);
    return fmaf(0.5f, th, 0.5f);
}
__device__ __forceinline__ float tanh_mufu(float x) {
    float th; TANHA(th, x);
    return th;
}

// =====================================================================
// Kernel 1 (persistent): x_gates = x @ W_ih^T + b_ih -> g_xg[t][B][G]
// 148 CTAs x 512 threads. W_ih^T resident. Tiles: 64 rows x 384 cols,
// thread tile 4 rows x 12 cols, x duplicated -> zero packing.
// =====================================================================
#define NT1 ((B_ * T_) / 64)             // 7680 tiles
#define K1_GRID 148
#define K1_ITER ((NT1 + K1_GRID - 1) / K1_GRID)   // 52
#define XDS 136                          // xd row stride (floats)
#define K1_SMEM ((64 * G_ + 64 * XDS + G_) * 4)   // 134656 B

__global__ __launch_bounds__(512, 1) void k1_xgates(
    const float* __restrict__ x,
    const float* __restrict__ Wih,
    const float* __restrict__ bih)
{
    extern __shared__ float sm[];
    float* Wt = sm;               // [64][384]  WihT[i][col']
    float* xd = Wt + 64 * G_;     // [64][XDS]  x dup: [i][2r],[i][2r+1]
    float* bI = xd + 64 * XDS;    // [384] reordered bias

    const int tid = threadIdx.x;

    // One-time: W_ih reordered+transposed, bias reordered
    for (int idx = tid; idx < G_ * I_; idx += 512) {
        int g = idx >> 6, i = idx & 63;
        Wt[i * G_ + ((g & 127) * 3 + (g >> 7))] = Wih[idx];
    }
    for (int g = tid; g < G_; g += 512)
        bI[(g & 127) * 3 + (g >> 7)] = bih[g];

    const int mblk = tid & 15;       // 16 row blocks of 4
    const int jblk = tid >> 4;       // 32 col blocks of 12
    const int m0 = mblk * 4;
    const int c0 = jblk * 12;

    for (int it = 0; it < K1_ITER; it++) {
        const int tt = blockIdx.x + it * K1_GRID;
        if (tt >= NT1) break;
        const size_t r0 = (size_t)tt * 64;

        __syncthreads();   // previous tile's xd reads complete
        for (int idx = tid; idx < 64 * 16; idx += 512) {
            int r = idx >> 4, i4 = idx & 15;
            float4 v = *(const float4*)(x + (r0 + r) * I_ + 4 * i4);
            *(float2*)(xd + (4 * i4 + 0) * XDS + 2 * r) = make_float2(v.x, v.x);
            *(float2*)(xd + (4 * i4 + 1) * XDS + 2 * r) = make_float2(v.y, v.y);
            *(float2*)(xd + (4 * i4 + 2) * XDS + 2 * r) = make_float2(v.z, v.z);
            *(float2*)(xd + (4 * i4 + 3) * XDS + 2 * r) = make_float2(v.w, v.w);
        }
        __syncthreads();

        unsigned long long acc[4][6];
        #pragma unroll
        for (int c = 0; c < 6; c++) {
            unsigned long long bp = *(const unsigned long long*)(bI + c0 + 2 * c);
            #pragma unroll
            for (int p = 0; p < 4; p++) acc[p][c] = bp;
        }

        #pragma unroll 8
        for (int k = 0; k < 64; k++) {
            const float* xrow = xd + k * XDS + 8 * mblk;   // 4 dup pairs
            ulonglong2 xa = *(const ulonglong2*)(xrow);
            ulonglong2 xb = *(const ulonglong2*)(xrow + 4);
            unsigned long long hp[4] = {xa.x, xa.y, xb.x, xb.y};
            const float* wrow = Wt + k * G_ + c0;
            ulonglong2 wa = *(const ulonglong2*)(wrow);
            ulonglong2 wb = *(const ulonglong2*)(wrow + 4);
            ulonglong2 wc = *(const ulonglong2*)(wrow + 8);
            unsigned long long wp[6] = {wa.x, wa.y, wb.x, wb.y, wc.x, wc.y};
            #pragma unroll
            for (int p = 0; p < 4; p++) {
                #pragma unroll
                for (int c = 0; c < 6; c++) FMA2(acc[p][c], hp[p], wp[c]);
            }
        }

        #pragma unroll
        for (int p = 0; p < 4; p++) {
            float v[12];
            #pragma unroll
            for (int c = 0; c < 6; c++) UNPACK2(v[2 * c], v[2 * c + 1], acc[p][c]);
            unsigned int r = (unsigned int)(r0 + m0 + p);
            unsigned int b = r / T_, t = r % T_;
            float* dst = g_xg + ((size_t)t * B_ + b) * G_ + c0;
            *(float4*)(dst)     = make_float4(v[0], v[1], v[2],  v[3]);
            *(float4*)(dst + 4) = make_float4(v[4], v[5], v[6],  v[7]);
            *(float4*)(dst + 8) = make_float4(v[8], v[9], v[10], v[11]);
        }
    }
}

// =====================================================================
// Kernel 2: recurrence, split-K lane pairs. 128 CTAs x 512 threads,
// 32 batch rows/CTA. Tile 4 rows x 12 cols per lane PAIR (lane, lane^16):
// khalf=0 does even k, khalf=1 odd k; shfl_xor(16) reduction;
// elementwise split 2 rows per lane. Double-buffered h, ONE sync/step.
// =====================================================================
#define WS 388   // Wt row stride: 388 mod 32 = 4 -> even/odd k rows hit
                 // disjoint banks (conflict-free w loads)
#define K2_SMEM ((128 * WS + 2 * 128 * 32) * 4)   // 231424 B

__global__ __launch_bounds__(512, 1) void k2_recur(
    const float* __restrict__ Whh,
    const float* __restrict__ bhh,
    float* __restrict__ out,      // [B, T, H]
    float* __restrict__ hT_out)   // [B, H]
{
    extern __shared__ float sm[];
    float* Wt    = sm;                    // [128][WS]  WhhT[k][col']
    float* hbuf0 = Wt + 128 * WS;         // [128][32]  h, buffer 0
    float* hbuf1 = hbuf0 + 128 * 32;      // [128][32]  h, buffer 1

    const int tid = threadIdx.x;
    const size_t b0 = (size_t)blockIdx.x * 32;

    for (int idx = tid; idx < G_ * H_; idx += 512) {
        int g = idx >> 7, k = idx & 127;
        Wt[k * WS + ((g & 127) * 3 + (g >> 7))] = Whh[idx];
    }
    for (int idx = tid; idx < 128 * 32; idx += 512) hbuf0[idx] = 0.0f;
    __syncthreads();

    const int lane  = tid & 31;
    const int warp  = tid >> 5;
    const int khalf = lane >> 4;          // 0: even k, 1: odd k
    const int sub   = lane & 15;
    const int idx   = warp * 16 + sub;    // 0..255 tile index
    const int mblk  = idx & 7;            // 8 blocks of 4 rows
    const int jblk  = idx >> 3;           // 32 blocks of 12 cols
    const int m0 = mblk * 4;
    const int c0 = jblk * 12;
    const int j0 = jblk * 4;
    const size_t rowa = b0 + m0 + 2 * khalf;   // this lane's 2 output rows

    // Bias pairs for cols c0..c0+11, gathered from gmem (reorder inverse:
    // col' = j*3+gate  ->  orig g = gate*128 + j)
    unsigned long long bias[6];
    #pragma unroll
    for (int c2 = 0; c2 < 6; c2++) {
        int ca = c0 + 2 * c2, cb = ca + 1;
        float lo = bhh[(ca % 3) * 128 + (ca / 3)];
        float hi = bhh[(cb % 3) * 128 + (cb / 3)];
        PACKAB(bias[c2], lo, hi);
        if (khalf) bias[c2] = 0ull;   // avoid double-count in reduction
    }

    float hprev[2][4];
    #pragma unroll
    for (int mi = 0; mi < 2; mi++)
        #pragma unroll
        for (int ji = 0; ji < 4; ji++) hprev[mi][ji] = 0.0f;

    for (int t = 0; t < T_; t++) {
        float* cur = (t & 1) ? hbuf1 : hbuf0;
        float* nxt = (t & 1) ? hbuf0 : hbuf1;

        // Prefetch input-side gate values for this lane's 2 rows
        float xf[2][12];
        #pragma unroll
        for (int mi = 0; mi < 2; mi++) {
            const float* p = g_xg + ((size_t)t * B_ + rowa + mi) * G_ + c0;
            float4 a = *(const float4*)(p);
            float4 b = *(const float4*)(p + 4);
            float4 c = *(const float4*)(p + 8);
            xf[mi][0] = a.x; xf[mi][1]  = a.y; xf[mi][2]  = a.z; xf[mi][3]  = a.w;
            xf[mi][4] = b.x; xf[mi][5]  = b.y; xf[mi][6]  = b.z; xf[mi][7]  = b.w;
            xf[mi][8] = c.x; xf[mi][9]  = c.y; xf[mi][10] = c.z; xf[mi][11] = c.w;
        }

        unsigned long long acc[4][6];
        #pragma unroll
        for (int r = 0; r < 4; r++)
            #pragma unroll
            for (int c = 0; c < 6; c++) acc[r][c] = bias[c];

        // Split-K loop: this lane covers k = 2*i + khalf
        const float* hbase = cur + khalf * 32 + m0;
        const float* wbase = Wt + khalf * WS + c0;
        #pragma unroll 8
        for (int i = 0; i < 64; i++) {
            float4 hv = *(const float4*)(hbase + i * 64);
            const float* wr = wbase + i * (2 * WS);
            ulonglong2 wa = *(const ulonglong2*)(wr);
            ulonglong2 wb = *(const ulonglong2*)(wr + 4);
            ulonglong2 wc = *(const ulonglong2*)(wr + 8);
            unsigned long long hp[4];
            PACK2(hp[0], hv.x); PACK2(hp[1], hv.y);
            PACK2(hp[2], hv.z); PACK2(hp[3], hv.w);
            unsigned long long wp[6] = {wa.x, wa.y, wb.x, wb.y, wc.x, wc.y};
            #pragma unroll
            for (int r = 0; r < 4; r++) {
                #pragma unroll
                for (int c = 0; c < 6; c++) FMA2(acc[r][c], hp[r], wp[c]);
            }
        }

        // Cross-lane reduction: send partner the rows IT owns, keep mine.
        // khalf=0 owns rows 0-1 (acc[0],acc[1]); khalf=1 owns rows 2-3.
        unsigned long long own[2][6], tot[2][6];
        #pragma unroll
        for (int c = 0; c < 6; c++) {
            unsigned long long s0 = khalf ? acc[0][c] : acc[2][c];
            unsigned long long s1 = khalf ? acc[1][c] : acc[3][c];
            unsigned long long r0 = __shfl_xor_sync(0xffffffffu, s0, 16);
            unsigned long long r1 = __shfl_xor_sync(0xffffffffu, s1, 16);
            own[0][c] = khalf ? acc[2][c] : acc[0][c];
            own[1][c] = khalf ? acc[3][c] : acc[1][c];
            ADD2(own[0][c], r0);
            ADD2(own[1][c], r1);
            tot[0][c] = own[0][c];
            tot[1][c] = own[1][c];
        }

        float hg[2][12];
        #pragma unroll
        for (int r = 0; r < 2; r++)
            #pragma unroll
            for (int c = 0; c < 6; c++)
                UNPACK2(hg[r][2 * c], hg[r][2 * c + 1], tot[r][c]);

        #pragma unroll
        for (int mi = 0; mi < 2; mi++) {
            float o[4];
            #pragma unroll
            for (int ji = 0; ji < 4; ji++) {
                float r = sigmoid_mufu(xf[mi][ji * 3 + 0] + hg[mi][ji * 3 + 0]);
                float z = sigmoid_mufu(xf[mi][ji * 3 + 1] + hg[mi][ji * 3 + 1]);
                float n = tanh_mufu(xf[mi][ji * 3 + 2] + r * hg[mi][ji * 3 + 2]);
                float h = n + z * (hprev[mi][ji] - n);
                hprev[mi][ji] = h;
                o[ji] = h;
            }
            *(float4*)(out + ((rowa + mi) * (size_t)T_ + t) * H_ + j0) =
                make_float4(o[0], o[1], o[2], o[3]);
        }

        // Publish this lane's 2 rows into the other buffer
        #pragma unroll
        for (int ji = 0; ji < 4; ji++)
            *(float2*)(nxt + (j0 + ji) * 32 + m0 + 2 * khalf) =
                make_float2(hprev[0][ji], hprev[1][ji]);
        __syncthreads();   // covers RAW (nxt) and WAR (cur)
    }

    #pragma unroll
    for (int mi = 0; mi < 2; mi++)
        *(float4*)(hT_out + (rowa + mi) * H_ + j0) =
            make_float4(hprev[mi][0], hprev[mi][1], hprev[mi][2], hprev[mi][3]);
}

extern "C" void kernel_launch(void* const* d_in, const int* in_sizes, int n_in,
                              void* d_out, int out_size)
{
    const float* x   = (const float*)d_in[0];
    const float* Wih = (const float*)d_in[1];
    const float* Whh = (const float*)d_in[2];
    const float* bih = (const float*)d_in[3];
    const float* bhh = (const float*)d_in[4];

    float* out = (float*)d_out;                       // [B, T, H]
    float* hT  = out + (size_t)B_ * T_ * H_;          // [B, H]

    cudaFuncSetAttribute(k1_xgates, cudaFuncAttributeMaxDynamicSharedMemorySize, K1_SMEM);
    cudaFuncSetAttribute(k2_recur,  cudaFuncAttributeMaxDynamicSharedMemorySize, K2_SMEM);

    k1_xgates<<<K1_GRID, 512, K1_SMEM>>>(x, Wih, bih);
    k2_recur<<<B_ / 32, 512, K2_SMEM>>>(Whh, bhh, out, hT);
}

// round 10
// speedup vs baseline: 2.2206x; 1.4381x over previous
#include <cuda_runtime.h>
#include <cstdint>

#define B_ 4096
#define T_ 120
#define I_ 64
#define H_ 128
#define G_ 384   // 3*H

// Input-side gate pre-activations, layout [t][B][G], natural gate-blocked
// cols g = gate*128 + j. Bias fold: b_ih (all gates) + b_hh (r,z ONLY —
// the n-gate's b_hh is multiplied by r in the GRU and is added in K2).
__device__ float g_xg[(size_t)B_ * T_ * G_];

// ---------------- f32x2 helpers (K1) ----------------
#define FMA2(d, a, b) \
    asm("fma.rn.f32x2 %0, %1, %2, %0;" : "+l"(d) : "l"(a), "l"(b))

#define UNPACK2(lo, hi, p) do {                                     \
    unsigned int _l, _h;                                            \
    asm("mov.b64 {%0, %1}, %2;" : "=r"(_l), "=r"(_h) : "l"(p));     \
    (lo) = __uint_as_float(_l); (hi) = __uint_as_float(_h);         \
} while (0)

#define TANHA(y, x) asm("tanh.approx.f32 %0, %1;" : "=f"(y) : "f"(x))

__device__ __forceinline__ float sigmoid_mufu(float x) {
    float th; TANHA(th, 0.5f * x);
    return fmaf(0.5f, th, 0.5f);
}
__device__ __forceinline__ float tanh_mufu(float x) {
    float th; TANHA(th, x);
    return th;
}

// ---------------- bf16 helpers (K2) ----------------
// pack two floats -> bf16x2 (lo_ in low half, hi_ in high half)
#define PBF2(r, lo_, hi_) \
    asm("cvt.rn.bf16x2.f32 %0, %1, %2;" : "=r"(r) : "f"(hi_), "f"(lo_))

#define MMAB(acc, a0, a1, a2, a3, b0, b1)                                 \
    asm volatile("mma.sync.aligned.m16n8k16.row.col.f32.bf16.bf16.f32 "   \
        "{%0,%1,%2,%3}, {%4,%5,%6,%7}, {%8,%9}, {%0,%1,%2,%3};"           \
        : "+f"((acc)[0]), "+f"((acc)[1]), "+f"((acc)[2]), "+f"((acc)[3])  \
        : "r"(a0), "r"(a1), "r"(a2), "r"(a3), "r"(b0), "r"(b1))

// =====================================================================
// Kernel 1 (persistent): x_gates = x @ W_ih^T + b_ih (+ b_hh for r,z)
// 148 CTAs x 512 threads, W_ih^T resident, natural gate-blocked cols.
// =====================================================================
#define NT1 ((B_ * T_) / 64)
#define K1_GRID 148
#define K1_ITER ((NT1 + K1_GRID - 1) / K1_GRID)
#define XDS 136
#define K1_SMEM ((64 * G_ + 64 * XDS + G_) * 4)

__global__ __launch_bounds__(512, 1) void k1_xgates(
    const float* __restrict__ x,
    const float* __restrict__ Wih,
    const float* __restrict__ bih,
    const float* __restrict__ bhh)
{
    extern __shared__ float sm[];
    float* Wt = sm;               // [64][384]  WihT[i][g]
    float* xd = Wt + 64 * G_;     // [64][XDS]  x dup pairs
    float* bI = xd + 64 * XDS;    // [384]

    const int tid = threadIdx.x;

    for (int idx = tid; idx < G_ * I_; idx += 512) {
        int g = idx >> 6, i = idx & 63;
        Wt[i * G_ + g] = Wih[idx];
    }
    for (int g = tid; g < G_; g += 512)
        bI[g] = bih[g] + (g < 2 * H_ ? bhh[g] : 0.0f);   // FIX: n-gate b_hh
                                                          // scales with r
    const int mblk = tid & 15;
    const int jblk = tid >> 4;
    const int m0 = mblk * 4;
    const int c0 = jblk * 12;

    for (int it = 0; it < K1_ITER; it++) {
        const int tt = blockIdx.x + it * K1_GRID;
        if (tt >= NT1) break;
        const size_t r0 = (size_t)tt * 64;

        __syncthreads();
        for (int idx = tid; idx < 64 * 16; idx += 512) {
            int r = idx >> 4, i4 = idx & 15;
            float4 v = *(const float4*)(x + (r0 + r) * I_ + 4 * i4);
            *(float2*)(xd + (4 * i4 + 0) * XDS + 2 * r) = make_float2(v.x, v.x);
            *(float2*)(xd + (4 * i4 + 1) * XDS + 2 * r) = make_float2(v.y, v.y);
            *(float2*)(xd + (4 * i4 + 2) * XDS + 2 * r) = make_float2(v.z, v.z);
            *(float2*)(xd + (4 * i4 + 3) * XDS + 2 * r) = make_float2(v.w, v.w);
        }
        __syncthreads();

        unsigned long long acc[4][6];
        #pragma unroll
        for (int c = 0; c < 6; c++) {
            unsigned long long bp = *(const unsigned long long*)(bI + c0 + 2 * c);
            #pragma unroll
            for (int p = 0; p < 4; p++) acc[p][c] = bp;
        }

        #pragma unroll 8
        for (int k = 0; k < 64; k++) {
            const float* xrow = xd + k * XDS + 8 * mblk;
            ulonglong2 xa = *(const ulonglong2*)(xrow);
            ulonglong2 xb = *(const ulonglong2*)(xrow + 4);
            unsigned long long hp[4] = {xa.x, xa.y, xb.x, xb.y};
            const float* wrow = Wt + k * G_ + c0;
            ulonglong2 wa = *(const ulonglong2*)(wrow);
            ulonglong2 wb = *(const ulonglong2*)(wrow + 4);
            ulonglong2 wc = *(const ulonglong2*)(wrow + 8);
            unsigned long long wp[6] = {wa.x, wa.y, wb.x, wb.y, wc.x, wc.y};
            #pragma unroll
            for (int p = 0; p < 4; p++) {
                #pragma unroll
                for (int c = 0; c < 6; c++) FMA2(acc[p][c], hp[p], wp[c]);
            }
        }

        #pragma unroll
        for (int p = 0; p < 4; p++) {
            float v[12];
            #pragma unroll
            for (int c = 0; c < 6; c++) UNPACK2(v[2 * c], v[2 * c + 1], acc[p][c]);
            unsigned int r = (unsigned int)(r0 + m0 + p);
            unsigned int b = r / T_, t = r % T_;
            float* dst = g_xg + ((size_t)t * B_ + b) * G_ + c0;
            *(float4*)(dst)     = make_float4(v[0], v[1], v[2],  v[3]);
            *(float4*)(dst + 4) = make_float4(v[4], v[5], v[6],  v[7]);
            *(float4*)(dst + 8) = make_float4(v[8], v[9], v[10], v[11]);
        }
    }
}

// =====================================================================
// Kernel 2 (mma.sync bf16x3): recurrence. 128 CTAs x 256 threads,
// 32 batch rows/CTA. hg = h @ W_hh^T via Whi*hhi + Whi*hlo + Wlo*hhi.
// Warp (mt,u): rows 16mt..+16, units 32u..+32, ALL 3 gates ->
// (r,z,n,h_prev) colocated per thread; h_prev in registers.
// n gate: tanh(xn + r*(hg_n + b_hh_n)).
// =====================================================================
#define WPK_HALF 98304                        // one split: 384 tiles * 256B
#define HB_OFF   (2 * WPK_HALF)               // 196608
#define HB_SPLIT 8704                         // 32 rows * 272B
#define HB_BUF   (2 * HB_SPLIT)               // 17408
#define K2M_SMEM (HB_OFF + 2 * HB_BUF)        // 231424

__global__ __launch_bounds__(256, 1) void k2_recur_mma(
    const float* __restrict__ Whh,
    const float* __restrict__ bhh,
    float* __restrict__ out,      // [B, T, H]
    float* __restrict__ hT_out)   // [B, H]
{
    extern __shared__ char smem[];
    const int tid  = threadIdx.x;
    const int lane = tid & 31, wid = tid >> 5;
    const int gr   = lane >> 2, tig = lane & 3;   // groupID, thread-in-group
    const int mt   = wid & 1;                     // m-tile (16 rows)
    const int u    = wid >> 1;                    // unit block (32 units)
    const size_t b0r = (size_t)blockIdx.x * 32;

    // ---- pack W_hh into bf16 hi/lo fragment tiles ----
    for (int idx = tid; idx < G_ * H_; idx += 256) {
        int n = idx >> 7, k = idx & 127;
        int gg = n >> 7, j = n & 127;
        int uu = j >> 5, nt = (j >> 3) & 3, col = j & 7;
        int kt = k >> 4, kin = k & 15;
        int tg = (kin >> 1) & 3, reg = kin >> 3, half = kin & 1;
        int TI = ((kt * 4 + uu) * 3 + gg) * 4 + nt;
        int byte = TI * 256 + (col * 4 + tg) * 8 + reg * 4 + half * 2;
        float w = Whh[idx];
        unsigned short hb; asm("cvt.rn.bf16.f32 %0, %1;" : "=h"(hb) : "f"(w));
        float hf = __uint_as_float((uint32_t)hb << 16);
        float rem = w - hf;
        unsigned short lb; asm("cvt.rn.bf16.f32 %0, %1;" : "=h"(lb) : "f"(rem));
        *(unsigned short*)(smem + byte)            = hb;
        *(unsigned short*)(smem + WPK_HALF + byte) = lb;
    }
    for (int i = tid; i < HB_BUF / 4; i += 256)
        *(uint32_t*)(smem + HB_OFF + 4 * i) = 0u;
    __syncthreads();

    // n-gate hidden bias for this thread's 8 columns
    float2 bn[4];
    #pragma unroll
    for (int nt = 0; nt < 4; nt++)
        bn[nt] = *(const float2*)(bhh + 2 * H_ + u * 32 + nt * 8 + 2 * tig);

    const char* wbh = smem + u * 12 * 256 + lane * 8;
    const char* wbl = wbh + WPK_HALF;

    float hprev[4][4];
    #pragma unroll
    for (int nt = 0; nt < 4; nt++)
        #pragma unroll
        for (int d = 0; d < 4; d++) hprev[nt][d] = 0.0f;

    const int r0 = mt * 16 + gr;

    for (int t = 0; t < T_; t++) {
        const char* hb  = smem + HB_OFF + (t & 1) * HB_BUF;
        const char* hbn = smem + HB_OFF + ((t + 1) & 1) * HB_BUF;

        float2 xf[2][3][4];
        {
            const float* xgp = g_xg + ((size_t)t * B_ + b0r + r0) * G_
                               + u * 32 + 2 * tig;
            #pragma unroll
            for (int rh = 0; rh < 2; rh++)
                #pragma unroll
                for (int gg = 0; gg < 3; gg++)
                    #pragma unroll
                    for (int nt = 0; nt < 4; nt++)
                        xf[rh][gg][nt] = *(const float2*)
                            (xgp + (size_t)rh * 8 * G_ + gg * 128 + nt * 8);
        }

        float acc[3][4][4];
        #pragma unroll
        for (int gg = 0; gg < 3; gg++)
            #pragma unroll
            for (int nt = 0; nt < 4; nt++)
                #pragma unroll
                for (int d = 0; d < 4; d++) acc[gg][nt][d] = 0.0f;

        #pragma unroll 2
        for (int kt = 0; kt < 8; kt++) {
            const char* ha = hb + r0 * 272 + (kt * 8 + tig) * 4;
            uint32_t ah0 = *(const uint32_t*)(ha);
            uint32_t ah1 = *(const uint32_t*)(ha + 8 * 272);
            uint32_t ah2 = *(const uint32_t*)(ha + 16);
            uint32_t ah3 = *(const uint32_t*)(ha + 8 * 272 + 16);
            const char* hl = ha + HB_SPLIT;
            uint32_t al0 = *(const uint32_t*)(hl);
            uint32_t al1 = *(const uint32_t*)(hl + 8 * 272);
            uint32_t al2 = *(const uint32_t*)(hl + 16);
            uint32_t al3 = *(const uint32_t*)(hl + 8 * 272 + 16);

            const char* wkh = wbh + kt * 12288;
            const char* wkl = wbl + kt * 12288;
            #pragma unroll
            for (int gg = 0; gg < 3; gg++) {
                #pragma unroll
                for (int nt = 0; nt < 4; nt++) {
                    uint2 bh = *(const uint2*)(wkh + gg * 1024 + nt * 256);
                    uint2 bl = *(const uint2*)(wkl + gg * 1024 + nt * 256);
                    MMAB(acc[gg][nt], ah0, ah1, ah2, ah3, bh.x, bh.y);
                    MMAB(acc[gg][nt], al0, al1, al2, al3, bh.x, bh.y);
                    MMAB(acc[gg][nt], ah0, ah1, ah2, ah3, bl.x, bl.y);
                }
            }
        }

        #pragma unroll
        for (int nt = 0; nt < 4; nt++) {
            #pragma unroll
            for (int rh = 0; rh < 2; rh++) {
                float h2[2];
                #pragma unroll
                for (int cc = 0; cc < 2; cc++) {
                    int d = rh * 2 + cc;
                    float xr = cc ? xf[rh][0][nt].y : xf[rh][0][nt].x;
                    float xz = cc ? xf[rh][1][nt].y : xf[rh][1][nt].x;
                    float xn = cc ? xf[rh][2][nt].y : xf[rh][2][nt].x;
                    float bnv = cc ? bn[nt].y : bn[nt].x;
                    float r = sigmoid_mufu(xr + acc[0][nt][d]);
                    float z = sigmoid_mufu(xz + acc[1][nt][d]);
                    float n = tanh_mufu(xn + r * (acc[2][nt][d] + bnv));
                    float h = n + z * (hprev[nt][d] - n);
                    hprev[nt][d] = h;
                    h2[cc] = h;
                }
                uint32_t whi; PBF2(whi, h2[0], h2[1]);
                float h0r = __uint_as_float(whi << 16);
                float h1r = __uint_as_float(whi & 0xffff0000u);
                uint32_t wlo; PBF2(wlo, h2[0] - h0r, h2[1] - h1r);

                int row = r0 + rh * 8;
                char* hw = (char*)hbn + row * 272 + (u * 16 + nt * 4 + tig) * 4;
                *(uint32_t*)hw = whi;
                *(uint32_t*)(hw + HB_SPLIT) = wlo;

                *(float2*)(out + (b0r + row) * (size_t)(T_ * H_)
                           + (size_t)t * H_ + u * 32 + nt * 8 + 2 * tig) =
                    make_float2(h2[0], h2[1]);
            }
        }
        __syncthreads();
    }

    #pragma unroll
    for (int nt = 0; nt < 4; nt++)
        #pragma unroll
        for (int rh = 0; rh < 2; rh++)
            *(float2*)(hT_out + (b0r + r0 + rh * 8) * H_
                       + u * 32 + nt * 8 + 2 * tig) =
                make_float2(hprev[nt][rh * 2], hprev[nt][rh * 2 + 1]);
}

extern "C" void kernel_launch(void* const* d_in, const int* in_sizes, int n_in,
                              void* d_out, int out_size)
{
    const float* x   = (const float*)d_in[0];
    const float* Wih = (const float*)d_in[1];
    const float* Whh = (const float*)d_in[2];
    const float* bih = (const float*)d_in[3];
    const float* bhh = (const float*)d_in[4];

    float* out = (float*)d_out;                       // [B, T, H]
    float* hT  = out + (size_t)B_ * T_ * H_;          // [B, H]

    cudaFuncSetAttribute(k1_xgates,    cudaFuncAttributeMaxDynamicSharedMemorySize, K1_SMEM);
    cudaFuncSetAttribute(k2_recur_mma, cudaFuncAttributeMaxDynamicSharedMemorySize, K2M_SMEM);

    k1_xgates<<<K1_GRID, 512, K1_SMEM>>>(x, Wih, bih, bhh);
    k2_recur_mma<<<B_ / 32, 256, K2M_SMEM>>>(Whh, bhh, out, hT);
}

// round 11
// speedup vs baseline: 2.6239x; 1.1816x over previous
#include <cuda_runtime.h>
#include <cstdint>

#define B_ 4096
#define T_ 120
#define I_ 64
#define H_ 128
#define G_ 384   // 3*H

// Input-side gate pre-activations, layout [t][B][G], natural gate-blocked
// cols g = gate*128 + j. Bias fold: b_ih (all gates) + b_hh (r,z ONLY —
// the n-gate's b_hh is multiplied by r in the GRU and is added in K2).
__device__ float g_xg[(size_t)B_ * T_ * G_];

#define TANHA(y, x) asm("tanh.approx.f32 %0, %1;" : "=f"(y) : "f"(x))

__device__ __forceinline__ float sigmoid_mufu(float x) {
    float th; TANHA(th, 0.5f * x);
    return fmaf(0.5f, th, 0.5f);
}
__device__ __forceinline__ float tanh_mufu(float x) {
    float th; TANHA(th, x);
    return th;
}

// pack two floats -> bf16x2 (lo_ in low half, hi_ in high half)
#define PBF2(r, lo_, hi_) \
    asm("cvt.rn.bf16x2.f32 %0, %1, %2;" : "=r"(r) : "f"(hi_), "f"(lo_))

#define MMAB(acc, a0, a1, a2, a3, b0, b1)                                 \
    asm volatile("mma.sync.aligned.m16n8k16.row.col.f32.bf16.bf16.f32 "   \
        "{%0,%1,%2,%3}, {%4,%5,%6,%7}, {%8,%9}, {%0,%1,%2,%3};"           \
        : "+f"((acc)[0]), "+f"((acc)[1]), "+f"((acc)[2]), "+f"((acc)[3])  \
        : "r"(a0), "r"(a1), "r"(a2), "r"(a3), "r"(b0), "r"(b1))

// =====================================================================
// Kernel 1 (persistent, mma.sync bf16x3):
//   x_gates = x @ W_ih^T + b_ih (+ b_hh for r,z)  -> g_xg[t][B][G]
// 148 CTAs x 256 threads. W_ih hi/lo fragment tiles resident in smem.
// Iter: 64-row x-tile -> bf16 hi/lo fragments -> 288 MMA/warp -> fp32 out.
// Warp (mt 0..3, uh 0..1): rows 16*mt..+16, cols 192*uh..+192 (24 n8-tiles).
// =====================================================================
#define NT1 ((B_ * T_) / 64)             // 7680 tiles of 64 rows
#define K1_GRID 148
#define K1_ITER ((NT1 + K1_GRID - 1) / K1_GRID)   // 52

#define W1_HALF 49152                    // 4 kt * 48 nt * 256B
#define X1_OFF  (2 * W1_HALF)            // 98304
#define X1_HALF 9216                     // 64 rows * 36 words * 4B
#define B1_OFF  (X1_OFF + 2 * X1_HALF)   // 116736
#define K1_SMEM (B1_OFF + G_ * 4)        // 118272

__global__ __launch_bounds__(256, 1) void k1_xgates(
    const float* __restrict__ x,
    const float* __restrict__ Wih,
    const float* __restrict__ bih,
    const float* __restrict__ bhh)
{
    extern __shared__ char smem[];
    const int tid  = threadIdx.x;
    const int lane = tid & 31, wid = tid >> 5;
    const int gr   = lane >> 2, tig = lane & 3;
    const int mt   = wid & 3;             // row block (16 rows)
    const int uh   = wid >> 2;            // col half (192 cols = 24 n8-tiles)

    // ---- one-time: W_ih -> bf16 hi/lo fragment tiles ----
    // tile TI = kt*48 + (n>>3); within tile: (col*4+tg)*8 + reg*4 + half*2
    for (int idx = tid; idx < G_ * I_; idx += 256) {
        int n = idx >> 6, k = idx & 63;
        int nt = n >> 3, col = n & 7;
        int kt = k >> 4, kin = k & 15;
        int tg = (kin >> 1) & 3, reg = kin >> 3, half = kin & 1;
        int byte = (kt * 48 + nt) * 256 + (col * 4 + tg) * 8 + reg * 4 + half * 2;
        float w = Wih[idx];
        unsigned short hb; asm("cvt.rn.bf16.f32 %0, %1;" : "=h"(hb) : "f"(w));
        float hf = __uint_as_float((uint32_t)hb << 16);
        float rem = w - hf;
        unsigned short lb; asm("cvt.rn.bf16.f32 %0, %1;" : "=h"(lb) : "f"(rem));
        *(unsigned short*)(smem + byte)           = hb;
        *(unsigned short*)(smem + W1_HALF + byte) = lb;
    }
    {   // bias: b_ih everywhere + b_hh for r,z only (n-gate b_hh scales w/ r)
        float* bI = (float*)(smem + B1_OFF);
        for (int g = tid; g < G_; g += 256)
            bI[g] = bih[g] + (g < 2 * H_ ? bhh[g] : 0.0f);
    }

    const char* wbh = smem + uh * 24 * 256 + lane * 8;
    const char* wbl = wbh + W1_HALF;
    char* xh = smem + X1_OFF;
    const float* bI = (const float*)(smem + B1_OFF);

    for (int it = 0; it < K1_ITER; it++) {
        const int tt = blockIdx.x + it * K1_GRID;
        if (tt >= NT1) break;
        const size_t r0 = (size_t)tt * 64;

        // ---- load + convert x tile into hi/lo fragment smem ----
        __syncthreads();   // WAR: previous iter's x reads done
        for (int idx = tid; idx < 64 * 32; idx += 256) {
            int row = idx >> 5, kp = idx & 31;
            float2 v = *(const float2*)(x + (r0 + row) * I_ + 2 * kp);
            uint32_t whi; PBF2(whi, v.x, v.y);
            float v0r = __uint_as_float(whi << 16);
            float v1r = __uint_as_float(whi & 0xffff0000u);
            uint32_t wlo; PBF2(wlo, v.x - v0r, v.y - v1r);
            int w = (row * 36 + kp) * 4;
            *(uint32_t*)(xh + w)           = whi;
            *(uint32_t*)(xh + X1_HALF + w) = wlo;
        }
        __syncthreads();

        float acc[24][4];
        #pragma unroll
        for (int nt = 0; nt < 24; nt++)
            #pragma unroll
            for (int d = 0; d < 4; d++) acc[nt][d] = 0.0f;

        #pragma unroll
        for (int kt = 0; kt < 4; kt++) {
            const char* ha = xh + ((mt * 16 + gr) * 36 + kt * 8 + tig) * 4;
            uint32_t ah0 = *(const uint32_t*)(ha);
            uint32_t ah1 = *(const uint32_t*)(ha + 8 * 144);
            uint32_t ah2 = *(const uint32_t*)(ha + 16);
            uint32_t ah3 = *(const uint32_t*)(ha + 8 * 144 + 16);
            const char* hl = ha + X1_HALF;
            uint32_t al0 = *(const uint32_t*)(hl);
            uint32_t al1 = *(const uint32_t*)(hl + 8 * 144);
            uint32_t al2 = *(const uint32_t*)(hl + 16);
            uint32_t al3 = *(const uint32_t*)(hl + 8 * 144 + 16);

            const char* wkh = wbh + kt * 48 * 256;
            const char* wkl = wbl + kt * 48 * 256;
            #pragma unroll
            for (int nt = 0; nt < 24; nt++) {
                uint2 bh = *(const uint2*)(wkh + nt * 256);
                uint2 bl = *(const uint2*)(wkl + nt * 256);
                MMAB(acc[nt], ah0, ah1, ah2, ah3, bh.x, bh.y);
                MMAB(acc[nt], al0, al1, al2, al3, bh.x, bh.y);
                MMAB(acc[nt], ah0, ah1, ah2, ah3, bl.x, bl.y);
            }
        }

        // ---- epilogue: add bias, store fp32 to g_xg[t][B][G] ----
        {
            unsigned int ra = (unsigned int)(r0 + mt * 16 + gr);
            unsigned int rb = ra + 8;
            unsigned int ba = ra / T_, ta = ra % T_;
            unsigned int bb = rb / T_, tb2 = rb % T_;
            float* da = g_xg + ((size_t)ta * B_ + ba) * G_ + uh * 192 + 2 * tig;
            float* db = g_xg + ((size_t)tb2 * B_ + bb) * G_ + uh * 192 + 2 * tig;
            #pragma unroll
            for (int nt = 0; nt < 24; nt++) {
                float2 bi = *(const float2*)(bI + uh * 192 + nt * 8 + 2 * tig);
                *(float2*)(da + nt * 8) =
                    make_float2(acc[nt][0] + bi.x, acc[nt][1] + bi.y);
                *(float2*)(db + nt * 8) =
                    make_float2(acc[nt][2] + bi.x, acc[nt][3] + bi.y);
            }
        }
    }
}

// =====================================================================
// Kernel 2 (mma.sync bf16x3): recurrence. 128 CTAs x 256 threads,
// 32 batch rows/CTA. hg = h @ W_hh^T via Whi*hhi + Whi*hlo + Wlo*hhi.
// Warp (mt,u): rows 16mt..+16, units 32u..+32, ALL 3 gates.
// n gate: tanh(xn + r*(hg_n + b_hh_n)). (unchanged from round 10)
// =====================================================================
#define WPK_HALF 98304
#define HB_OFF   (2 * WPK_HALF)
#define HB_SPLIT 8704
#define HB_BUF   (2 * HB_SPLIT)
#define K2M_SMEM (HB_OFF + 2 * HB_BUF)

__global__ __launch_bounds__(256, 1) void k2_recur_mma(
    const float* __restrict__ Whh,
    const float* __restrict__ bhh,
    float* __restrict__ out,      // [B, T, H]
    float* __restrict__ hT_out)   // [B, H]
{
    extern __shared__ char smem[];
    const int tid  = threadIdx.x;
    const int lane = tid & 31, wid = tid >> 5;
    const int gr   = lane >> 2, tig = lane & 3;
    const int mt   = wid & 1;
    const int u    = wid >> 1;
    const size_t b0r = (size_t)blockIdx.x * 32;

    for (int idx = tid; idx < G_ * H_; idx += 256) {
        int n = idx >> 7, k = idx & 127;
        int gg = n >> 7, j = n & 127;
        int uu = j >> 5, nt = (j >> 3) & 3, col = j & 7;
        int kt = k >> 4, kin = k & 15;
        int tg = (kin >> 1) & 3, reg = kin >> 3, half = kin & 1;
        int TI = ((kt * 4 + uu) * 3 + gg) * 4 + nt;
        int byte = TI * 256 + (col * 4 + tg) * 8 + reg * 4 + half * 2;
        float w = Whh[idx];
        unsigned short hb; asm("cvt.rn.bf16.f32 %0, %1;" : "=h"(hb) : "f"(w));
        float hf = __uint_as_float((uint32_t)hb << 16);
        float rem = w - hf;
        unsigned short lb; asm("cvt.rn.bf16.f32 %0, %1;" : "=h"(lb) : "f"(rem));
        *(unsigned short*)(smem + byte)            = hb;
        *(unsigned short*)(smem + WPK_HALF + byte) = lb;
    }
    for (int i = tid; i < HB_BUF / 4; i += 256)
        *(uint32_t*)(smem + HB_OFF + 4 * i) = 0u;
    __syncthreads();

    float2 bn[4];
    #pragma unroll
    for (int nt = 0; nt < 4; nt++)
        bn[nt] = *(const float2*)(bhh + 2 * H_ + u * 32 + nt * 8 + 2 * tig);

    const char* wbh = smem + u * 12 * 256 + lane * 8;
    const char* wbl = wbh + WPK_HALF;

    float hprev[4][4];
    #pragma unroll
    for (int nt = 0; nt < 4; nt++)
        #pragma unroll
        for (int d = 0; d < 4; d++) hprev[nt][d] = 0.0f;

    const int r0 = mt * 16 + gr;

    for (int t = 0; t < T_; t++) {
        const char* hb  = smem + HB_OFF + (t & 1) * HB_BUF;
        const char* hbn = smem + HB_OFF + ((t + 1) & 1) * HB_BUF;

        float2 xf[2][3][4];
        {
            const float* xgp = g_xg + ((size_t)t * B_ + b0r + r0) * G_
                               + u * 32 + 2 * tig;
            #pragma unroll
            for (int rh = 0; rh < 2; rh++)
                #pragma unroll
                for (int gg = 0; gg < 3; gg++)
                    #pragma unroll
                    for (int nt = 0; nt < 4; nt++)
                        xf[rh][gg][nt] = *(const float2*)
                            (xgp + (size_t)rh * 8 * G_ + gg * 128 + nt * 8);
        }

        float acc[3][4][4];
        #pragma unroll
        for (int gg = 0; gg < 3; gg++)
            #pragma unroll
            for (int nt = 0; nt < 4; nt++)
                #pragma unroll
                for (int d = 0; d < 4; d++) acc[gg][nt][d] = 0.0f;

        #pragma unroll 2
        for (int kt = 0; kt < 8; kt++) {
            const char* ha = hb + r0 * 272 + (kt * 8 + tig) * 4;
            uint32_t ah0 = *(const uint32_t*)(ha);
            uint32_t ah1 = *(const uint32_t*)(ha + 8 * 272);
            uint32_t ah2 = *(const uint32_t*)(ha + 16);
            uint32_t ah3 = *(const uint32_t*)(ha + 8 * 272 + 16);
            const char* hl = ha + HB_SPLIT;
            uint32_t al0 = *(const uint32_t*)(hl);
            uint32_t al1 = *(const uint32_t*)(hl + 8 * 272);
            uint32_t al2 = *(const uint32_t*)(hl + 16);
            uint32_t al3 = *(const uint32_t*)(hl + 8 * 272 + 16);

            const char* wkh = wbh + kt * 12288;
            const char* wkl = wbl + kt * 12288;
            #pragma unroll
            for (int gg = 0; gg < 3; gg++) {
                #pragma unroll
                for (int nt = 0; nt < 4; nt++) {
                    uint2 bh = *(const uint2*)(wkh + gg * 1024 + nt * 256);
                    uint2 bl = *(const uint2*)(wkl + gg * 1024 + nt * 256);
                    MMAB(acc[gg][nt], ah0, ah1, ah2, ah3, bh.x, bh.y);
                    MMAB(acc[gg][nt], al0, al1, al2, al3, bh.x, bh.y);
                    MMAB(acc[gg][nt], ah0, ah1, ah2, ah3, bl.x, bl.y);
                }
            }
        }

        #pragma unroll
        for (int nt = 0; nt < 4; nt++) {
            #pragma unroll
            for (int rh = 0; rh < 2; rh++) {
                float h2[2];
                #pragma unroll
                for (int cc = 0; cc < 2; cc++) {
                    int d = rh * 2 + cc;
                    float xr = cc ? xf[rh][0][nt].y : xf[rh][0][nt].x;
                    float xz = cc ? xf[rh][1][nt].y : xf[rh][1][nt].x;
                    float xn = cc ? xf[rh][2][nt].y : xf[rh][2][nt].x;
                    float bnv = cc ? bn[nt].y : bn[nt].x;
                    float r = sigmoid_mufu(xr + acc[0][nt][d]);
                    float z = sigmoid_mufu(xz + acc[1][nt][d]);
                    float n = tanh_mufu(xn + r * (acc[2][nt][d] + bnv));
                    float h = n + z * (hprev[nt][d] - n);
                    hprev[nt][d] = h;
                    h2[cc] = h;
                }
                uint32_t whi; PBF2(whi, h2[0], h2[1]);
                float h0r = __uint_as_float(whi << 16);
                float h1r = __uint_as_float(whi & 0xffff0000u);
                uint32_t wlo; PBF2(wlo, h2[0] - h0r, h2[1] - h1r);

                int row = r0 + rh * 8;
                char* hw = (char*)hbn + row * 272 + (u * 16 + nt * 4 + tig) * 4;
                *(uint32_t*)hw = whi;
                *(uint32_t*)(hw + HB_SPLIT) = wlo;

                *(float2*)(out + (b0r + row) * (size_t)(T_ * H_)
                           + (size_t)t * H_ + u * 32 + nt * 8 + 2 * tig) =
                    make_float2(h2[0], h2[1]);
            }
        }
        __syncthreads();
    }

    #pragma unroll
    for (int nt = 0; nt < 4; nt++)
        #pragma unroll
        for (int rh = 0; rh < 2; rh++)
            *(float2*)(hT_out + (b0r + r0 + rh * 8) * H_
                       + u * 32 + nt * 8 + 2 * tig) =
                make_float2(hprev[nt][rh * 2], hprev[nt][rh * 2 + 1]);
}

extern "C" void kernel_launch(void* const* d_in, const int* in_sizes, int n_in,
                              void* d_out, int out_size)
{
    const float* x   = (const float*)d_in[0];
    const float* Wih = (const float*)d_in[1];
    const float* Whh = (const float*)d_in[2];
    const float* bih = (const float*)d_in[3];
    const float* bhh = (const float*)d_in[4];

    float* out = (float*)d_out;                       // [B, T, H]
    float* hT  = out + (size_t)B_ * T_ * H_;          // [B, H]

    cudaFuncSetAttribute(k1_xgates,    cudaFuncAttributeMaxDynamicSharedMemorySize, K1_SMEM);
    cudaFuncSetAttribute(k2_recur_mma, cudaFuncAttributeMaxDynamicSharedMemorySize, K2M_SMEM);

    k1_xgates<<<K1_GRID, 256, K1_SMEM>>>(x, Wih, bih, bhh);
    k2_recur_mma<<<B_ / 32, 256, K2M_SMEM>>>(Whh, bhh, out, hT);
}

// round 12
// speedup vs baseline: 2.7616x; 1.0525x over previous
#include <cuda_runtime.h>
#include <cstdint>

#define B_ 4096
#define T_ 120
#define I_ 64
#define H_ 128
#define G_ 384   // 3*H

// Input-side gate pre-activations, layout [t][B][G], natural gate-blocked
// cols g = gate*128 + j. Bias fold: b_ih (all gates) + b_hh (r,z ONLY —
// the n-gate's b_hh is multiplied by r in the GRU and is added in K2).
__device__ float g_xg[(size_t)B_ * T_ * G_];

#define TANHA(y, x) asm("tanh.approx.f32 %0, %1;" : "=f"(y) : "f"(x))

__device__ __forceinline__ float sigmoid_mufu(float x) {
    float th; TANHA(th, 0.5f * x);
    return fmaf(0.5f, th, 0.5f);
}
__device__ __forceinline__ float tanh_mufu(float x) {
    float th; TANHA(th, x);
    return th;
}

// pack two floats -> bf16x2 (lo_ in low half, hi_ in high half)
#define PBF2(r, lo_, hi_) \
    asm("cvt.rn.bf16x2.f32 %0, %1, %2;" : "=r"(r) : "f"(hi_), "f"(lo_))

#define MMAB(acc, a0, a1, a2, a3, b0, b1)                                 \
    asm volatile("mma.sync.aligned.m16n8k16.row.col.f32.bf16.bf16.f32 "   \
        "{%0,%1,%2,%3}, {%4,%5,%6,%7}, {%8,%9}, {%0,%1,%2,%3};"           \
        : "+f"((acc)[0]), "+f"((acc)[1]), "+f"((acc)[2]), "+f"((acc)[3])  \
        : "r"(a0), "r"(a1), "r"(a2), "r"(a3), "r"(b0), "r"(b1))

// =====================================================================
// Kernel 1 (persistent, mma.sync bf16x3, software-pipelined):
//   x_gates = x @ W_ih^T + b_ih (+ b_hh for r,z)  -> g_xg[t][B][G]
// 148 CTAs x 512 threads. W_ih hi/lo fragment tiles resident in smem.
// Per iter: convert prefetched x regs -> smem frags; prefetch NEXT tile's
// x during MMA (LDG hidden). Warp (mt 0..3, u 0..3): rows 16*mt..+16,
// cols 96*u..+96 (12 n8-tiles), 144 MMA/warp.
// =====================================================================
#define NT1 ((B_ * T_) / 64)             // 7680 tiles of 64 rows
#define K1_GRID 148
#define K1_ITER ((NT1 + K1_GRID - 1) / K1_GRID)   // 52

#define W1_HALF 49152                    // 4 kt * 48 nt * 256B
#define X1_OFF  (2 * W1_HALF)            // 98304
#define X1_HALF 9216                     // 64 rows * 36 words * 4B
#define B1_OFF  (X1_OFF + 2 * X1_HALF)   // 116736
#define K1_SMEM (B1_OFF + G_ * 4)        // 118272

__global__ __launch_bounds__(512, 1) void k1_xgates(
    const float* __restrict__ x,
    const float* __restrict__ Wih,
    const float* __restrict__ bih,
    const float* __restrict__ bhh)
{
    extern __shared__ char smem[];
    const int tid  = threadIdx.x;
    const int lane = tid & 31, wid = tid >> 5;
    const int gr   = lane >> 2, tig = lane & 3;
    const int mt   = wid & 3;             // row block (16 rows)
    const int u    = wid >> 2;            // col quarter (96 cols = 12 n8-tiles)

    // ---- one-time: W_ih -> bf16 hi/lo fragment tiles ----
    for (int idx = tid; idx < G_ * I_; idx += 512) {
        int n = idx >> 6, k = idx & 63;
        int nt = n >> 3, col = n & 7;
        int kt = k >> 4, kin = k & 15;
        int tg = (kin >> 1) & 3, reg = kin >> 3, half = kin & 1;
        int byte = (kt * 48 + nt) * 256 + (col * 4 + tg) * 8 + reg * 4 + half * 2;
        float w = Wih[idx];
        unsigned short hb; asm("cvt.rn.bf16.f32 %0, %1;" : "=h"(hb) : "f"(w));
        float hf = __uint_as_float((uint32_t)hb << 16);
        float rem = w - hf;
        unsigned short lb; asm("cvt.rn.bf16.f32 %0, %1;" : "=h"(lb) : "f"(rem));
        *(unsigned short*)(smem + byte)           = hb;
        *(unsigned short*)(smem + W1_HALF + byte) = lb;
    }
    {   // bias: b_ih everywhere + b_hh for r,z only
        float* bW = (float*)(smem + B1_OFF);
        for (int g = tid; g < G_; g += 512)
            bW[g] = bih[g] + (g < 2 * H_ ? bhh[g] : 0.0f);
    }

    const char* wbh = smem + u * 12 * 256 + lane * 8;
    const char* wbl = wbh + W1_HALF;
    char* xh = smem + X1_OFF;
    const float* bI = (const float*)(smem + B1_OFF);

    // ---- prefetch tile 0 into registers ----
    float2 xr[4];
    if (blockIdx.x < NT1) {
        const size_t rn = (size_t)blockIdx.x * 64;
        #pragma unroll
        for (int j = 0; j < 4; j++) {
            int idx = tid + j * 512;
            int row = idx >> 5, kp = idx & 31;
            xr[j] = *(const float2*)(x + (rn + row) * I_ + 2 * kp);
        }
    }

    for (int it = 0; it < K1_ITER; it++) {
        const int tt = blockIdx.x + it * K1_GRID;
        if (tt >= NT1) break;
        const size_t r0 = (size_t)tt * 64;

        if (it) __syncthreads();   // WAR: prior iter's xh reads done
        // convert prefetched regs -> hi/lo fragment smem
        #pragma unroll
        for (int j = 0; j < 4; j++) {
            int idx = tid + j * 512;
            int row = idx >> 5, kp = idx & 31;
            uint32_t whi; PBF2(whi, xr[j].x, xr[j].y);
            float v0r = __uint_as_float(whi << 16);
            float v1r = __uint_as_float(whi & 0xffff0000u);
            uint32_t wlo; PBF2(wlo, xr[j].x - v0r, xr[j].y - v1r);
            int w = (row * 36 + kp) * 4;
            *(uint32_t*)(xh + w)           = whi;
            *(uint32_t*)(xh + X1_HALF + w) = wlo;
        }
        __syncthreads();           // xh (and, at it=0, W/bias) ready

        // prefetch NEXT tile's x — LDG latency hidden under MMA below
        const int ttn = tt + K1_GRID;
        if (ttn < NT1) {
            const size_t rn = (size_t)ttn * 64;
            #pragma unroll
            for (int j = 0; j < 4; j++) {
                int idx = tid + j * 512;
                int row = idx >> 5, kp = idx & 31;
                xr[j] = *(const float2*)(x + (rn + row) * I_ + 2 * kp);
            }
        }

        float acc[12][4];
        #pragma unroll
        for (int nt = 0; nt < 12; nt++)
            #pragma unroll
            for (int d = 0; d < 4; d++) acc[nt][d] = 0.0f;

        #pragma unroll
        for (int kt = 0; kt < 4; kt++) {
            const char* ha = xh + ((mt * 16 + gr) * 36 + kt * 8 + tig) * 4;
            uint32_t ah0 = *(const uint32_t*)(ha);
            uint32_t ah1 = *(const uint32_t*)(ha + 8 * 144);
            uint32_t ah2 = *(const uint32_t*)(ha + 16);
            uint32_t ah3 = *(const uint32_t*)(ha + 8 * 144 + 16);
            const char* hl = ha + X1_HALF;
            uint32_t al0 = *(const uint32_t*)(hl);
            uint32_t al1 = *(const uint32_t*)(hl + 8 * 144);
            uint32_t al2 = *(const uint32_t*)(hl + 16);
            uint32_t al3 = *(const uint32_t*)(hl + 8 * 144 + 16);

            const char* wkh = wbh + kt * 48 * 256;
            const char* wkl = wbl + kt * 48 * 256;
            #pragma unroll
            for (int nt = 0; nt < 12; nt++) {
                uint2 bh = *(const uint2*)(wkh + nt * 256);
                uint2 bl = *(const uint2*)(wkl + nt * 256);
                MMAB(acc[nt], ah0, ah1, ah2, ah3, bh.x, bh.y);
                MMAB(acc[nt], al0, al1, al2, al3, bh.x, bh.y);
                MMAB(acc[nt], ah0, ah1, ah2, ah3, bl.x, bl.y);
            }
        }

        // ---- epilogue: add bias, store fp32 to g_xg[t][B][G] ----
        {
            unsigned int ra = (unsigned int)(r0 + mt * 16 + gr);
            unsigned int rb = ra + 8;
            unsigned int ba = ra / T_, ta = ra % T_;
            unsigned int bb = rb / T_, tb2 = rb % T_;
            float* da = g_xg + ((size_t)ta * B_ + ba) * G_ + u * 96 + 2 * tig;
            float* db = g_xg + ((size_t)tb2 * B_ + bb) * G_ + u * 96 + 2 * tig;
            #pragma unroll
            for (int nt = 0; nt < 12; nt++) {
                float2 bi = *(const float2*)(bI + u * 96 + nt * 8 + 2 * tig);
                *(float2*)(da + nt * 8) =
                    make_float2(acc[nt][0] + bi.x, acc[nt][1] + bi.y);
                *(float2*)(db + nt * 8) =
                    make_float2(acc[nt][2] + bi.x, acc[nt][3] + bi.y);
            }
        }
    }
}

// =====================================================================
// Kernel 2 (mma.sync bf16x3): recurrence. 128 CTAs x 256 threads,
// 32 batch rows/CTA. Out-STGs moved AFTER the barrier (h in registers)
// to shorten the per-step pre-barrier critical path.
// =====================================================================
#define WPK_HALF 98304
#define HB_OFF   (2 * WPK_HALF)
#define HB_SPLIT 8704
#define HB_BUF   (2 * HB_SPLIT)
#define K2M_SMEM (HB_OFF + 2 * HB_BUF)

__global__ __launch_bounds__(256, 1) void k2_recur_mma(
    const float* __restrict__ Whh,
    const float* __restrict__ bhh,
    float* __restrict__ out,      // [B, T, H]
    float* __restrict__ hT_out)   // [B, H]
{
    extern __shared__ char smem[];
    const int tid  = threadIdx.x;
    const int lane = tid & 31, wid = tid >> 5;
    const int gr   = lane >> 2, tig = lane & 3;
    const int mt   = wid & 1;
    const int u    = wid >> 1;
    const size_t b0r = (size_t)blockIdx.x * 32;

    for (int idx = tid; idx < G_ * H_; idx += 256) {
        int n = idx >> 7, k = idx & 127;
        int gg = n >> 7, j = n & 127;
        int uu = j >> 5, nt = (j >> 3) & 3, col = j & 7;
        int kt = k >> 4, kin = k & 15;
        int tg = (kin >> 1) & 3, reg = kin >> 3, half = kin & 1;
        int TI = ((kt * 4 + uu) * 3 + gg) * 4 + nt;
        int byte = TI * 256 + (col * 4 + tg) * 8 + reg * 4 + half * 2;
        float w = Whh[idx];
        unsigned short hb; asm("cvt.rn.bf16.f32 %0, %1;" : "=h"(hb) : "f"(w));
        float hf = __uint_as_float((uint32_t)hb << 16);
        float rem = w - hf;
        unsigned short lb; asm("cvt.rn.bf16.f32 %0, %1;" : "=h"(lb) : "f"(rem));
        *(unsigned short*)(smem + byte)            = hb;
        *(unsigned short*)(smem + WPK_HALF + byte) = lb;
    }
    for (int i = tid; i < HB_BUF / 4; i += 256)
        *(uint32_t*)(smem + HB_OFF + 4 * i) = 0u;
    __syncthreads();

    float2 bn[4];
    #pragma unroll
    for (int nt = 0; nt < 4; nt++)
        bn[nt] = *(const float2*)(bhh + 2 * H_ + u * 32 + nt * 8 + 2 * tig);

    const char* wbh = smem + u * 12 * 256 + lane * 8;
    const char* wbl = wbh + WPK_HALF;

    float hprev[4][4];
    #pragma unroll
    for (int nt = 0; nt < 4; nt++)
        #pragma unroll
        for (int d = 0; d < 4; d++) hprev[nt][d] = 0.0f;

    const int r0 = mt * 16 + gr;

    for (int t = 0; t < T_; t++) {
        const char* hb  = smem + HB_OFF + (t & 1) * HB_BUF;
        const char* hbn = smem + HB_OFF + ((t + 1) & 1) * HB_BUF;

        float2 xf[2][3][4];
        {
            const float* xgp = g_xg + ((size_t)t * B_ + b0r + r0) * G_
                               + u * 32 + 2 * tig;
            #pragma unroll
            for (int rh = 0; rh < 2; rh++)
                #pragma unroll
                for (int gg = 0; gg < 3; gg++)
                    #pragma unroll
                    for (int nt = 0; nt < 4; nt++)
                        xf[rh][gg][nt] = *(const float2*)
                            (xgp + (size_t)rh * 8 * G_ + gg * 128 + nt * 8);
        }

        float acc[3][4][4];
        #pragma unroll
        for (int gg = 0; gg < 3; gg++)
            #pragma unroll
            for (int nt = 0; nt < 4; nt++)
                #pragma unroll
                for (int d = 0; d < 4; d++) acc[gg][nt][d] = 0.0f;

        #pragma unroll 2
        for (int kt = 0; kt < 8; kt++) {
            const char* ha = hb + r0 * 272 + (kt * 8 + tig) * 4;
            uint32_t ah0 = *(const uint32_t*)(ha);
            uint32_t ah1 = *(const uint32_t*)(ha + 8 * 272);
            uint32_t ah2 = *(const uint32_t*)(ha + 16);
            uint32_t ah3 = *(const uint32_t*)(ha + 8 * 272 + 16);
            const char* hl = ha + HB_SPLIT;
            uint32_t al0 = *(const uint32_t*)(hl);
            uint32_t al1 = *(const uint32_t*)(hl + 8 * 272);
            uint32_t al2 = *(const uint32_t*)(hl + 16);
            uint32_t al3 = *(const uint32_t*)(hl + 8 * 272 + 16);

            const char* wkh = wbh + kt * 12288;
            const char* wkl = wbl + kt * 12288;
            #pragma unroll
            for (int gg = 0; gg < 3; gg++) {
                #pragma unroll
                for (int nt = 0; nt < 4; nt++) {
                    uint2 bh = *(const uint2*)(wkh + gg * 1024 + nt * 256);
                    uint2 bl = *(const uint2*)(wkl + gg * 1024 + nt * 256);
                    MMAB(acc[gg][nt], ah0, ah1, ah2, ah3, bh.x, bh.y);
                    MMAB(acc[gg][nt], al0, al1, al2, al3, bh.x, bh.y);
                    MMAB(acc[gg][nt], ah0, ah1, ah2, ah3, bl.x, bl.y);
                }
            }
        }

        // elementwise update + publish h to smem (critical path only)
        #pragma unroll
        for (int nt = 0; nt < 4; nt++) {
            #pragma unroll
            for (int rh = 0; rh < 2; rh++) {
                float h2[2];
                #pragma unroll
                for (int cc = 0; cc < 2; cc++) {
                    int d = rh * 2 + cc;
                    float xr = cc ? xf[rh][0][nt].y : xf[rh][0][nt].x;
                    float xz = cc ? xf[rh][1][nt].y : xf[rh][1][nt].x;
                    float xn = cc ? xf[rh][2][nt].y : xf[rh][2][nt].x;
                    float bnv = cc ? bn[nt].y : bn[nt].x;
                    float r = sigmoid_mufu(xr + acc[0][nt][d]);
                    float z = sigmoid_mufu(xz + acc[1][nt][d]);
                    float n = tanh_mufu(xn + r * (acc[2][nt][d] + bnv));
                    float h = n + z * (hprev[nt][d] - n);
                    hprev[nt][d] = h;
                    h2[cc] = h;
                }
                uint32_t whi; PBF2(whi, h2[0], h2[1]);
                float h0r = __uint_as_float(whi << 16);
                float h1r = __uint_as_float(whi & 0xffff0000u);
                uint32_t wlo; PBF2(wlo, h2[0] - h0r, h2[1] - h1r);

                int row = r0 + rh * 8;
                char* hw = (char*)hbn + row * 272 + (u * 16 + nt * 4 + tig) * 4;
                *(uint32_t*)hw = whi;
                *(uint32_t*)(hw + HB_SPLIT) = wlo;
            }
        }
        __syncthreads();

        // out-stores AFTER the barrier — off the recurrence critical path
        #pragma unroll
        for (int nt = 0; nt < 4; nt++)
            #pragma unroll
            for (int rh = 0; rh < 2; rh++)
                *(float2*)(out + (b0r + r0 + rh * 8) * (size_t)(T_ * H_)
                           + (size_t)t * H_ + u * 32 + nt * 8 + 2 * tig) =
                    make_float2(hprev[nt][rh * 2], hprev[nt][rh * 2 + 1]);
    }

    #pragma unroll
    for (int nt = 0; nt < 4; nt++)
        #pragma unroll
        for (int rh = 0; rh < 2; rh++)
            *(float2*)(hT_out + (b0r + r0 + rh * 8) * H_
                       + u * 32 + nt * 8 + 2 * tig) =
                make_float2(hprev[nt][rh * 2], hprev[nt][rh * 2 + 1]);
}

extern "C" void kernel_launch(void* const* d_in, const int* in_sizes, int n_in,
                              void* d_out, int out_size)
{
    const float* x   = (const float*)d_in[0];
    const float* Wih = (const float*)d_in[1];
    const float* Whh = (const float*)d_in[2];
    const float* bih = (const float*)d_in[3];
    const float* bhh = (const float*)d_in[4];

    float* out = (float*)d_out;                       // [B, T, H]
    float* hT  = out + (size_t)B_ * T_ * H_;          // [B, H]

    cudaFuncSetAttribute(k1_xgates,    cudaFuncAttributeMaxDynamicSharedMemorySize, K1_SMEM);
    cudaFuncSetAttribute(k2_recur_mma, cudaFuncAttributeMaxDynamicSharedMemorySize, K2M_SMEM);

    k1_xgates<<<K1_GRID, 512, K1_SMEM>>>(x, Wih, bih, bhh);
    k2_recur_mma<<<B_ / 32, 256, K2M_SMEM>>>(Whh, bhh, out, hT);
}

// round 13
// speedup vs baseline: 4.0388x; 1.4625x over previous
#include <cuda_runtime.h>
#include <cstdint>

#define B_ 4096
#define T_ 120
#define I_ 64
#define H_ 128
#define G_ 384   // 3*H

// Input-side gate pre-activations, layout [B][T][G] (row = b*T + t —
// contiguous with K1's row tiles; K2 strides by T*G per batch row).
// Natural gate-blocked cols g = gate*128 + j. Bias fold: b_ih (all gates)
// + b_hh (r,z ONLY — n-gate's b_hh is multiplied by r; added in K2).
__device__ float g_xg[(size_t)B_ * T_ * G_];

#define TANHA(y, x) asm("tanh.approx.f32 %0, %1;" : "=f"(y) : "f"(x))

__device__ __forceinline__ float sigmoid_mufu(float x) {
    float th; TANHA(th, 0.5f * x);
    return fmaf(0.5f, th, 0.5f);
}
__device__ __forceinline__ float tanh_mufu(float x) {
    float th; TANHA(th, x);
    return th;
}

// pack two floats -> bf16x2 (lo_ in low half, hi_ in high half)
#define PBF2(r, lo_, hi_) \
    asm("cvt.rn.bf16x2.f32 %0, %1, %2;" : "=r"(r) : "f"(hi_), "f"(lo_))

#define MMAB(acc, a0, a1, a2, a3, b0, b1)                                 \
    asm volatile("mma.sync.aligned.m16n8k16.row.col.f32.bf16.bf16.f32 "   \
        "{%0,%1,%2,%3}, {%4,%5,%6,%7}, {%8,%9}, {%0,%1,%2,%3};"           \
        : "+f"((acc)[0]), "+f"((acc)[1]), "+f"((acc)[2]), "+f"((acc)[3])  \
        : "r"(a0), "r"(a1), "r"(a2), "r"(a3), "r"(b0), "r"(b1))

// =====================================================================
// Kernel 1 (persistent, mma.sync bf16x3, software-pipelined):
//   x_gates = x @ W_ih^T + b_ih (+ b_hh for r,z)  -> g_xg[B][T][G]
// 148 CTAs x 512 threads. Contiguous 96KB stores per iteration.
// =====================================================================
#define NT1 ((B_ * T_) / 64)             // 7680 tiles of 64 rows
#define K1_GRID 148
#define K1_ITER ((NT1 + K1_GRID - 1) / K1_GRID)   // 52

#define W1_HALF 49152                    // 4 kt * 48 nt * 256B
#define X1_OFF  (2 * W1_HALF)            // 98304
#define X1_HALF 9216                     // 64 rows * 36 words * 4B
#define B1_OFF  (X1_OFF + 2 * X1_HALF)   // 116736
#define K1_SMEM (B1_OFF + G_ * 4)        // 118272

__global__ __launch_bounds__(512, 1) void k1_xgates(
    const float* __restrict__ x,
    const float* __restrict__ Wih,
    const float* __restrict__ bih,
    const float* __restrict__ bhh)
{
    extern __shared__ char smem[];
    const int tid  = threadIdx.x;
    const int lane = tid & 31, wid = tid >> 5;
    const int gr   = lane >> 2, tig = lane & 3;
    const int mt   = wid & 3;             // row block (16 rows)
    const int u    = wid >> 2;            // col quarter (96 cols = 12 n8-tiles)

    // ---- one-time: W_ih -> bf16 hi/lo fragment tiles ----
    for (int idx = tid; idx < G_ * I_; idx += 512) {
        int n = idx >> 6, k = idx & 63;
        int nt = n >> 3, col = n & 7;
        int kt = k >> 4, kin = k & 15;
        int tg = (kin >> 1) & 3, reg = kin >> 3, half = kin & 1;
        int byte = (kt * 48 + nt) * 256 + (col * 4 + tg) * 8 + reg * 4 + half * 2;
        float w = Wih[idx];
        unsigned short hb; asm("cvt.rn.bf16.f32 %0, %1;" : "=h"(hb) : "f"(w));
        float hf = __uint_as_float((uint32_t)hb << 16);
        float rem = w - hf;
        unsigned short lb; asm("cvt.rn.bf16.f32 %0, %1;" : "=h"(lb) : "f"(rem));
        *(unsigned short*)(smem + byte)           = hb;
        *(unsigned short*)(smem + W1_HALF + byte) = lb;
    }
    {   // bias: b_ih everywhere + b_hh for r,z only
        float* bW = (float*)(smem + B1_OFF);
        for (int g = tid; g < G_; g += 512)
            bW[g] = bih[g] + (g < 2 * H_ ? bhh[g] : 0.0f);
    }

    const char* wbh = smem + u * 12 * 256 + lane * 8;
    const char* wbl = wbh + W1_HALF;
    char* xh = smem + X1_OFF;
    const float* bI = (const float*)(smem + B1_OFF);

    // ---- prefetch tile 0 into registers ----
    float2 xr[4];
    if (blockIdx.x < NT1) {
        const size_t rn = (size_t)blockIdx.x * 64;
        #pragma unroll
        for (int j = 0; j < 4; j++) {
            int idx = tid + j * 512;
            int row = idx >> 5, kp = idx & 31;
            xr[j] = *(const float2*)(x + (rn + row) * I_ + 2 * kp);
        }
    }

    for (int it = 0; it < K1_ITER; it++) {
        const int tt = blockIdx.x + it * K1_GRID;
        if (tt >= NT1) break;
        const size_t r0 = (size_t)tt * 64;

        if (it) __syncthreads();   // WAR: prior iter's xh reads done
        #pragma unroll
        for (int j = 0; j < 4; j++) {
            int idx = tid + j * 512;
            int row = idx >> 5, kp = idx & 31;
            uint32_t whi; PBF2(whi, xr[j].x, xr[j].y);
            float v0r = __uint_as_float(whi << 16);
            float v1r = __uint_as_float(whi & 0xffff0000u);
            uint32_t wlo; PBF2(wlo, xr[j].x - v0r, xr[j].y - v1r);
            int w = (row * 36 + kp) * 4;
            *(uint32_t*)(xh + w)           = whi;
            *(uint32_t*)(xh + X1_HALF + w) = wlo;
        }
        __syncthreads();

        // prefetch NEXT tile's x — hidden under MMA
        const int ttn = tt + K1_GRID;
        if (ttn < NT1) {
            const size_t rn = (size_t)ttn * 64;
            #pragma unroll
            for (int j = 0; j < 4; j++) {
                int idx = tid + j * 512;
                int row = idx >> 5, kp = idx & 31;
                xr[j] = *(const float2*)(x + (rn + row) * I_ + 2 * kp);
            }
        }

        float acc[12][4];
        #pragma unroll
        for (int nt = 0; nt < 12; nt++)
            #pragma unroll
            for (int d = 0; d < 4; d++) acc[nt][d] = 0.0f;

        #pragma unroll
        for (int kt = 0; kt < 4; kt++) {
            const char* ha = xh + ((mt * 16 + gr) * 36 + kt * 8 + tig) * 4;
            uint32_t ah0 = *(const uint32_t*)(ha);
            uint32_t ah1 = *(const uint32_t*)(ha + 8 * 144);
            uint32_t ah2 = *(const uint32_t*)(ha + 16);
            uint32_t ah3 = *(const uint32_t*)(ha + 8 * 144 + 16);
            const char* hl = ha + X1_HALF;
            uint32_t al0 = *(const uint32_t*)(hl);
            uint32_t al1 = *(const uint32_t*)(hl + 8 * 144);
            uint32_t al2 = *(const uint32_t*)(hl + 16);
            uint32_t al3 = *(const uint32_t*)(hl + 8 * 144 + 16);

            const char* wkh = wbh + kt * 48 * 256;
            const char* wkl = wbl + kt * 48 * 256;
            #pragma unroll
            for (int nt = 0; nt < 12; nt++) {
                uint2 bh = *(const uint2*)(wkh + nt * 256);
                uint2 bl = *(const uint2*)(wkl + nt * 256);
                MMAB(acc[nt], ah0, ah1, ah2, ah3, bh.x, bh.y);
                MMAB(acc[nt], al0, al1, al2, al3, bh.x, bh.y);
                MMAB(acc[nt], ah0, ah1, ah2, ah3, bl.x, bl.y);
            }
        }

        // ---- epilogue: add bias, store fp32; [B][T][G] -> row = r ----
        {
            const size_t ra = r0 + mt * 16 + gr;
            float* da = g_xg + ra * G_ + u * 96 + 2 * tig;
            float* db = da + (size_t)8 * G_;
            #pragma unroll
            for (int nt = 0; nt < 12; nt++) {
                float2 bi = *(const float2*)(bI + u * 96 + nt * 8 + 2 * tig);
                *(float2*)(da + nt * 8) =
                    make_float2(acc[nt][0] + bi.x, acc[nt][1] + bi.y);
                *(float2*)(db + nt * 8) =
                    make_float2(acc[nt][2] + bi.x, acc[nt][3] + bi.y);
            }
        }
    }
}

// =====================================================================
// Kernel 2 (mma.sync bf16x3): recurrence. 128 CTAs x 512 threads,
// 32 batch rows/CTA. Warp (mt 0..1, u 0..7): rows 16mt..+16,
// units 16u..+16 (2 n8-tiles), all 3 gates; 144 MMA/warp/step.
// n gate: tanh(xn + r*(hg_n + b_hh_n)).
// =====================================================================
#define WPK_HALF 98304
#define HB_OFF   (2 * WPK_HALF)
#define HB_SPLIT 8704
#define HB_BUF   (2 * HB_SPLIT)
#define K2M_SMEM (HB_OFF + 2 * HB_BUF)

__global__ __launch_bounds__(512, 1) void k2_recur_mma(
    const float* __restrict__ Whh,
    const float* __restrict__ bhh,
    float* __restrict__ out,      // [B, T, H]
    float* __restrict__ hT_out)   // [B, H]
{
    extern __shared__ char smem[];
    const int tid  = threadIdx.x;
    const int lane = tid & 31, wid = tid >> 5;
    const int gr   = lane >> 2, tig = lane & 3;
    const int mt   = wid & 1;                 // row block (16 rows)
    const int u    = wid >> 1;                // unit block (16 units), 0..7
    const size_t b0r = (size_t)blockIdx.x * 32;

    // W_hh -> bf16 hi/lo fragment tiles (same layout as round 10/11)
    for (int idx = tid; idx < G_ * H_; idx += 512) {
        int n = idx >> 7, k = idx & 127;
        int gg = n >> 7, j = n & 127;
        int uu = j >> 5, nt = (j >> 3) & 3, col = j & 7;
        int kt = k >> 4, kin = k & 15;
        int tg = (kin >> 1) & 3, reg = kin >> 3, half = kin & 1;
        int TI = ((kt * 4 + uu) * 3 + gg) * 4 + nt;
        int byte = TI * 256 + (col * 4 + tg) * 8 + reg * 4 + half * 2;
        float w = Whh[idx];
        unsigned short hb; asm("cvt.rn.bf16.f32 %0, %1;" : "=h"(hb) : "f"(w));
        float hf = __uint_as_float((uint32_t)hb << 16);
        float rem = w - hf;
        unsigned short lb; asm("cvt.rn.bf16.f32 %0, %1;" : "=h"(lb) : "f"(rem));
        *(unsigned short*)(smem + byte)            = hb;
        *(unsigned short*)(smem + WPK_HALF + byte) = lb;
    }
    for (int i = tid; i < HB_BUF / 4; i += 512)
        *(uint32_t*)(smem + HB_OFF + 4 * i) = 0u;
    __syncthreads();

    // this warp's W tile base: uu = u>>1, first nt = (u&1)*2
    const char* wbh = smem + (u >> 1) * 12 * 256 + (u & 1) * 512 + lane * 8;
    const char* wbl = wbh + WPK_HALF;

    float2 bn[2];
    #pragma unroll
    for (int nt = 0; nt < 2; nt++)
        bn[nt] = *(const float2*)(bhh + 2 * H_ + u * 16 + nt * 8 + 2 * tig);

    float hprev[2][4];
    #pragma unroll
    for (int nt = 0; nt < 2; nt++)
        #pragma unroll
        for (int d = 0; d < 4; d++) hprev[nt][d] = 0.0f;

    const int r0 = mt * 16 + gr;

    for (int t = 0; t < T_; t++) {
        const char* hb  = smem + HB_OFF + (t & 1) * HB_BUF;
        const char* hbn = smem + HB_OFF + ((t + 1) & 1) * HB_BUF;

        // x-gates for this warp's 2 rows x 3 gates x 2 n-tiles; [B][T][G]
        float2 xf[2][3][2];
        {
            const float* xgp = g_xg + ((b0r + r0) * (size_t)T_ + t) * G_
                               + u * 16 + 2 * tig;
            #pragma unroll
            for (int rh = 0; rh < 2; rh++)
                #pragma unroll
                for (int gg = 0; gg < 3; gg++)
                    #pragma unroll
                    for (int nt = 0; nt < 2; nt++)
                        xf[rh][gg][nt] = *(const float2*)
                            (xgp + (size_t)rh * 8 * T_ * G_ + gg * 128 + nt * 8);
        }

        float acc[3][2][4];
        #pragma unroll
        for (int gg = 0; gg < 3; gg++)
            #pragma unroll
            for (int nt = 0; nt < 2; nt++)
                #pragma unroll
                for (int d = 0; d < 4; d++) acc[gg][nt][d] = 0.0f;

        #pragma unroll 2
        for (int kt = 0; kt < 8; kt++) {
            const char* ha = hb + r0 * 272 + (kt * 8 + tig) * 4;
            uint32_t ah0 = *(const uint32_t*)(ha);
            uint32_t ah1 = *(const uint32_t*)(ha + 8 * 272);
            uint32_t ah2 = *(const uint32_t*)(ha + 16);
            uint32_t ah3 = *(const uint32_t*)(ha + 8 * 272 + 16);
            const char* hl = ha + HB_SPLIT;
            uint32_t al0 = *(const uint32_t*)(hl);
            uint32_t al1 = *(const uint32_t*)(hl + 8 * 272);
            uint32_t al2 = *(const uint32_t*)(hl + 16);
            uint32_t al3 = *(const uint32_t*)(hl + 8 * 272 + 16);

            const char* wkh = wbh + kt * 12288;
            const char* wkl = wbl + kt * 12288;
            #pragma unroll
            for (int gg = 0; gg < 3; gg++) {
                #pragma unroll
                for (int nt = 0; nt < 2; nt++) {
                    uint2 bh = *(const uint2*)(wkh + gg * 1024 + nt * 256);
                    uint2 bl = *(const uint2*)(wkl + gg * 1024 + nt * 256);
                    MMAB(acc[gg][nt], ah0, ah1, ah2, ah3, bh.x, bh.y);
                    MMAB(acc[gg][nt], al0, al1, al2, al3, bh.x, bh.y);
                    MMAB(acc[gg][nt], ah0, ah1, ah2, ah3, bl.x, bl.y);
                }
            }
        }

        #pragma unroll
        for (int nt = 0; nt < 2; nt++) {
            #pragma unroll
            for (int rh = 0; rh < 2; rh++) {
                float h2[2];
                #pragma unroll
                for (int cc = 0; cc < 2; cc++) {
                    int d = rh * 2 + cc;
                    float xr = cc ? xf[rh][0][nt].y : xf[rh][0][nt].x;
                    float xz = cc ? xf[rh][1][nt].y : xf[rh][1][nt].x;
                    float xn = cc ? xf[rh][2][nt].y : xf[rh][2][nt].x;
                    float bnv = cc ? bn[nt].y : bn[nt].x;
                    float r = sigmoid_mufu(xr + acc[0][nt][d]);
                    float z = sigmoid_mufu(xz + acc[1][nt][d]);
                    float n = tanh_mufu(xn + r * (acc[2][nt][d] + bnv));
                    float h = n + z * (hprev[nt][d] - n);
                    hprev[nt][d] = h;
                    h2[cc] = h;
                }
                uint32_t whi; PBF2(whi, h2[0], h2[1]);
                float h0r = __uint_as_float(whi << 16);
                float h1r = __uint_as_float(whi & 0xffff0000u);
                uint32_t wlo; PBF2(wlo, h2[0] - h0r, h2[1] - h1r);

                int row = r0 + rh * 8;
                // word index = unit/2 = (u*16 + nt*8 + 2*tig)/2
                char* hw = (char*)hbn + row * 272 + (u * 8 + nt * 4 + tig) * 4;
                *(uint32_t*)hw = whi;
                *(uint32_t*)(hw + HB_SPLIT) = wlo;

                *(float2*)(out + (b0r + row) * (size_t)(T_ * H_)
                           + (size_t)t * H_ + u * 16 + nt * 8 + 2 * tig) =
                    make_float2(h2[0], h2[1]);
            }
        }
        __syncthreads();
    }

    #pragma unroll
    for (int nt = 0; nt < 2; nt++)
        #pragma unroll
        for (int rh = 0; rh < 2; rh++)
            *(float2*)(hT_out + (b0r + r0 + rh * 8) * H_
                       + u * 16 + nt * 8 + 2 * tig) =
                make_float2(hprev[nt][rh * 2], hprev[nt][rh * 2 + 1]);
}

extern "C" void kernel_launch(void* const* d_in, const int* in_sizes, int n_in,
                              void* d_out, int out_size)
{
    const float* x   = (const float*)d_in[0];
    const float* Wih = (const float*)d_in[1];
    const float* Whh = (const float*)d_in[2];
    const float* bih = (const float*)d_in[3];
    const float* bhh = (const float*)d_in[4];

    float* out = (float*)d_out;                       // [B, T, H]
    float* hT  = out + (size_t)B_ * T_ * H_;          // [B, H]

    cudaFuncSetAttribute(k1_xgates,    cudaFuncAttributeMaxDynamicSharedMemorySize, K1_SMEM);
    cudaFuncSetAttribute(k2_recur_mma, cudaFuncAttributeMaxDynamicSharedMemorySize, K2M_SMEM);

    k1_xgates<<<K1_GRID, 512, K1_SMEM>>>(x, Wih, bih, bhh);
    k2_recur_mma<<<B_ / 32, 512, K2M_SMEM>>>(Whh, bhh, out, hT);
}